// round 1
// baseline (speedup 1.0000x reference)
#include <cuda_runtime.h>

// Problem dims
#define B_   32
#define T_   50
#define N_   100
#define D_   4
#define E_   9900          // N*(N-1)
#define BE_  316800        // B*E
#define H_   256           // hidden
#define NIN_ 200           // T*D

// Scratch (device globals; no allocation allowed)
__device__ float g_ehid [BE_ * H_];       // 324 MB
__device__ float g_xskip[BE_ * H_];       // 324 MB
__device__ float g_nodeA[B_ * N_ * H_];   // 3.3 MB
__device__ float g_nodeB[B_ * N_ * H_];   // 3.3 MB

enum { MODE_DIR = 0, MODE_X = 1, MODE_E2 = 2, MODE_E3 = 3 };

// C[M,NOUT] = act(gather_A[M,K] @ W[K,NOUT] + bias)
// Tiles: 128x128x8, 256 threads, 8x8 per thread, smem double-buffered.
template<int MODE, int K, int NOUT, bool RELU>
__global__ __launch_bounds__(256, 2)
void gemm_k(const float* __restrict__ A, const float* __restrict__ Aux,
            const float* __restrict__ W, const float* __restrict__ bias,
            float* __restrict__ C)
{
    constexpr int TM = 128, TN = 128, TK = 8;
    __shared__ float sA[2][TK][TM + 4];
    __shared__ float sB[2][TK][TN];

    const int tid = threadIdx.x;
    const int m0  = blockIdx.x * TM;
    const int n0  = blockIdx.y * TN;

    // A-tile loader mapping: each thread loads one float4 (row a_m, k-offset a_k)
    const int a_m = tid >> 1;
    const int a_k = (tid & 1) << 2;
    // B-tile loader mapping: one float4 per thread
    const int b_k = tid >> 5;
    const int b_n = (tid & 31) << 2;

    // Per-thread gather bases for its A row
    const int m = m0 + a_m;
    const float* pr = nullptr;
    const float* ps = nullptr;
    const float* px = nullptr;
    if (MODE == MODE_DIR) {
        pr = A + (size_t)m * K;
    } else if (MODE == MODE_X) {
        // x is (B,T,N,D); row (b,n), feature k=(t*D+d)
        int b = m / N_, n = m - b * N_;
        pr = A + (size_t)b * (T_ * N_ * D_) + (size_t)n * D_;   // + t*(N_*D_)
    } else {
        int b = m / E_, e = m - b * E_;
        int rcv = e / (N_ - 1), jj = e - rcv * (N_ - 1);
        int snd = jj + (jj >= rcv ? 1 : 0);
        pr = A + (size_t)(b * N_ + rcv) * H_;
        ps = A + (size_t)(b * N_ + snd) * H_;
        if (MODE == MODE_E3) px = Aux + (size_t)m * H_;
    }

    auto ldA = [&](int k0) -> float4 {
        const int k = k0 + a_k;
        if (MODE == MODE_DIR) {
            return *(const float4*)(pr + k);
        } else if (MODE == MODE_X) {
            return *(const float4*)(pr + (size_t)(k >> 2) * (N_ * D_));
        } else if (MODE == MODE_E2) {
            return (k < H_) ? *(const float4*)(pr + k)
                            : *(const float4*)(ps + (k - H_));
        } else { // MODE_E3
            if (k < H_)     return *(const float4*)(pr + k);
            if (k < 2 * H_) return *(const float4*)(ps + (k - H_));
            return *(const float4*)(px + (k - 2 * H_));
        }
    };
    auto ldB = [&](int k0) -> float4 {
        return *(const float4*)(W + (size_t)(k0 + b_k) * NOUT + n0 + b_n);
    };

    const int tx = tid & 15, ty = tid >> 4;
    float acc[8][8];
#pragma unroll
    for (int i = 0; i < 8; i++)
#pragma unroll
        for (int j = 0; j < 8; j++) acc[i][j] = 0.f;

    constexpr int S = K / TK;

    // stage 0 fill
    {
        float4 ra = ldA(0), rb = ldB(0);
        sA[0][a_k + 0][a_m] = ra.x;
        sA[0][a_k + 1][a_m] = ra.y;
        sA[0][a_k + 2][a_m] = ra.z;
        sA[0][a_k + 3][a_m] = ra.w;
        *(float4*)&sB[0][b_k][b_n] = rb;
    }
    __syncthreads();

    for (int s = 0; s < S; ++s) {
        const int cur = s & 1;
        float4 na, nb;
        if (s + 1 < S) { na = ldA((s + 1) * TK); nb = ldB((s + 1) * TK); }
#pragma unroll
        for (int k = 0; k < TK; ++k) {
            float4 a0 = *(const float4*)&sA[cur][k][ty * 8];
            float4 a1 = *(const float4*)&sA[cur][k][ty * 8 + 4];
            float4 b0 = *(const float4*)&sB[cur][k][tx * 8];
            float4 b1 = *(const float4*)&sB[cur][k][tx * 8 + 4];
            float av[8] = {a0.x, a0.y, a0.z, a0.w, a1.x, a1.y, a1.z, a1.w};
            float bv[8] = {b0.x, b0.y, b0.z, b0.w, b1.x, b1.y, b1.z, b1.w};
#pragma unroll
            for (int i = 0; i < 8; i++)
#pragma unroll
                for (int j = 0; j < 8; j++)
                    acc[i][j] = fmaf(av[i], bv[j], acc[i][j]);
        }
        if (s + 1 < S) {
            const int nxt = cur ^ 1;
            sA[nxt][a_k + 0][a_m] = na.x;
            sA[nxt][a_k + 1][a_m] = na.y;
            sA[nxt][a_k + 2][a_m] = na.z;
            sA[nxt][a_k + 3][a_m] = na.w;
            *(float4*)&sB[nxt][b_k][b_n] = nb;
        }
        __syncthreads();
    }

    // epilogue: bias (+relu), vectorized store
    float bb[8];
#pragma unroll
    for (int j = 0; j < 8; j++) bb[j] = bias[n0 + tx * 8 + j];
#pragma unroll
    for (int i = 0; i < 8; i++) {
        float v[8];
#pragma unroll
        for (int j = 0; j < 8; j++) {
            float t = acc[i][j] + bb[j];
            v[j] = RELU ? fmaxf(t, 0.f) : t;
        }
        float* crow = C + (size_t)(m0 + ty * 8 + i) * NOUT + n0 + tx * 8;
        float4 o0 = {v[0], v[1], v[2], v[3]};
        float4 o1 = {v[4], v[5], v[6], v[7]};
        *(float4*)(crow)     = o0;
        *(float4*)(crow + 4) = o1;
    }
}

// v[b,n,:] = mean over the 99 contiguous edges with recv==n, / N (per reference: /rec.shape[1]==N)
__global__ void agg_kernel(const float* __restrict__ e, float* __restrict__ v)
{
    const int bn = blockIdx.x;               // 0..B*N-1
    const int b  = bn / N_, n = bn - b * N_;
    const int c  = threadIdx.x;              // 0..255
    const float* base = e + ((size_t)b * E_ + (size_t)n * (N_ - 1)) * H_ + c;
    float s = 0.f;
#pragma unroll 9
    for (int k = 0; k < N_ - 1; ++k) s += base[(size_t)k * H_];
    v[(size_t)bn * H_ + c] = s * (1.0f / N_);
}

// out[m,0:4] = e2[m,:] @ wo + bo ; 32 rows per block, 128 threads
__global__ __launch_bounds__(128)
void out_kernel(const float* __restrict__ e2, const float* __restrict__ wo,
                const float* __restrict__ bo, float* __restrict__ out)
{
    __shared__ float sE[32][260];
    __shared__ float sW[H_ * 4];
    const int tid = threadIdx.x;
    const size_t row0 = (size_t)blockIdx.x * 32;

    for (int i = tid; i < H_ * 4; i += 128) sW[i] = wo[i];
    for (int i = tid; i < 32 * 64; i += 128) {
        int r = i >> 6, c4 = (i & 63) << 2;
        float4 t = *(const float4*)(e2 + (row0 + r) * H_ + c4);
        *(float4*)&sE[r][c4] = t;
    }
    __syncthreads();

    const int r = tid >> 2, j = tid & 3;
    float s = bo[j];
#pragma unroll 8
    for (int k = 0; k < H_; ++k) s = fmaf(sE[r][k], sW[k * 4 + j], s);
    out[(row0 + r) * 4 + j] = s;
}

extern "C" void kernel_launch(void* const* d_in, const int* in_sizes, int n_in,
                              void* d_out, int out_size)
{
    (void)in_sizes; (void)n_in; (void)out_size;
    const float* x   = (const float*)d_in[0];
    // d_in[1]=rec, d_in[2]=send : one-hot matrices, replaced by analytic indices
    const float* w1a = (const float*)d_in[3];
    const float* b1a = (const float*)d_in[4];
    const float* w1b = (const float*)d_in[5];
    const float* b1b = (const float*)d_in[6];
    const float* w2a = (const float*)d_in[7];
    const float* b2a = (const float*)d_in[8];
    const float* w2b = (const float*)d_in[9];
    const float* b2b = (const float*)d_in[10];
    const float* w3a = (const float*)d_in[11];
    const float* b3a = (const float*)d_in[12];
    const float* w3b = (const float*)d_in[13];
    const float* b3b = (const float*)d_in[14];
    const float* w4a = (const float*)d_in[15];
    const float* b4a = (const float*)d_in[16];
    const float* w4b = (const float*)d_in[17];
    const float* b4b = (const float*)d_in[18];
    const float* wo  = (const float*)d_in[19];
    const float* bo  = (const float*)d_in[20];
    float* out = (float*)d_out;

    float *ehid, *xskip, *nodeA, *nodeB;
    cudaGetSymbolAddress((void**)&ehid,  g_ehid);
    cudaGetSymbolAddress((void**)&xskip, g_xskip);
    cudaGetSymbolAddress((void**)&nodeA, g_nodeA);
    cudaGetSymbolAddress((void**)&nodeB, g_nodeB);

    const dim3 blk(256);
    const dim3 gNode(25, 2);     // 3200/128 x 256/128
    const dim3 gEdge(2475, 2);   // 316800/128 x 256/128

    // MLP1 on nodes: x(transposed gather) -> nodeA(hidden,relu) -> nodeB(h)
    gemm_k<MODE_X,  NIN_, H_, true ><<<gNode, blk>>>(x,     nullptr, w1a, b1a, nodeA);
    gemm_k<MODE_DIR, H_,  H_, false><<<gNode, blk>>>(nodeA, nullptr, w1b, b1b, nodeB);

    // MLP2 on edges: concat(h[recv],h[send]) -> ehid(relu) -> xskip (=x_skip)
    gemm_k<MODE_E2, 2*H_, H_, true ><<<gEdge, blk>>>(nodeB, nullptr, w2a, b2a, ehid);
    gemm_k<MODE_DIR, H_,  H_, false><<<gEdge, blk>>>(ehid,  nullptr, w2b, b2b, xskip);

    // Aggregate edges->nodes: nodeA = segsum(xskip)/N
    agg_kernel<<<B_ * N_, 256>>>(xskip, nodeA);

    // MLP3 on nodes: nodeA -> nodeB(hidden,relu) -> nodeA (=v)
    gemm_k<MODE_DIR, H_, H_, true ><<<gNode, blk>>>(nodeA, nullptr, w3a, b3a, nodeB);
    gemm_k<MODE_DIR, H_, H_, false><<<gNode, blk>>>(nodeB, nullptr, w3b, b3b, nodeA);

    // MLP4 on edges: concat(v[recv],v[send],x_skip) -> ehid(relu) -> xskip (=e2)
    gemm_k<MODE_E3, 3*H_, H_, true ><<<gEdge, blk>>>(nodeA, xskip, w4a, b4a, ehid);
    gemm_k<MODE_DIR, H_,  H_, false><<<gEdge, blk>>>(ehid,  nullptr, w4b, b4b, xskip);

    // Output head: e2 @ wo + bo
    out_kernel<<<BE_ / 32, 128>>>(xskip, wo, bo, out);
}

// round 2
// speedup vs baseline: 1.0523x; 1.0523x over previous
#include <cuda_runtime.h>

// Problem dims
#define B_   32
#define T_   50
#define N_   100
#define D_   4
#define E_   9900          // N*(N-1)
#define BE_  316800        // B*E
#define H_   256           // hidden
#define NIN_ 200           // T*D

// Scratch (device globals; no allocation allowed)
__device__ float g_ehid [BE_ * H_];       // 324 MB
__device__ float g_xskip[BE_ * H_];       // 324 MB
__device__ float g_nodeA[B_ * N_ * H_];   // 3.3 MB
__device__ float g_nodeB[B_ * N_ * H_];   // 3.3 MB

enum { MODE_DIR = 0, MODE_X = 1, MODE_E2 = 2, MODE_E3 = 3 };

typedef unsigned long long u64;

__device__ __forceinline__ u64 pk2(float lo, float hi) {
    u64 r; asm("mov.b64 %0, {%1, %2};" : "=l"(r) : "f"(lo), "f"(hi)); return r;
}
__device__ __forceinline__ void fma2(u64& d, u64 a, u64 b) {
    asm("fma.rn.f32x2 %0, %1, %2, %0;" : "+l"(d) : "l"(a), "l"(b));
}
__device__ __forceinline__ void unpk2(float& lo, float& hi, u64 v) {
    asm("mov.b64 {%0, %1}, %2;" : "=f"(lo), "=f"(hi) : "l"(v));
}

// C[M,NOUT] = act(gather_A[M,K] @ W[K,NOUT] + bias)
// Tiles: 128x128x8, 256 threads, 8x8 per thread (packed f32x2 FMA), smem double-buffered.
template<int MODE, int K, int NOUT, bool RELU>
__global__ __launch_bounds__(256, 2)
void gemm_k(const float* __restrict__ A, const float* __restrict__ Aux,
            const float* __restrict__ W, const float* __restrict__ bias,
            float* __restrict__ C)
{
    constexpr int TM = 128, TN = 128, TK = 8;
    __shared__ float sA[2][TK][TM + 4];
    __shared__ __align__(16) float sB[2][TK][TN];

    const int tid = threadIdx.x;
    const int m0  = blockIdx.x * TM;
    const int n0  = blockIdx.y * TN;

    // A-tile loader mapping: each thread loads one float4 (row a_m, k-offset a_k)
    const int a_m = tid >> 1;
    const int a_k = (tid & 1) << 2;
    // B-tile loader mapping: one float4 per thread
    const int b_k = tid >> 5;
    const int b_n = (tid & 31) << 2;

    // Per-thread gather bases for its A row
    const int m = m0 + a_m;
    const float* pr = nullptr;
    const float* ps = nullptr;
    const float* px = nullptr;
    if (MODE == MODE_DIR) {
        pr = A + (size_t)m * K;
    } else if (MODE == MODE_X) {
        // x is (B,T,N,D); row (b,n), feature k=(t*D+d)
        int b = m / N_, n = m - b * N_;
        pr = A + (size_t)b * (T_ * N_ * D_) + (size_t)n * D_;   // + t*(N_*D_)
    } else {
        int b = m / E_, e = m - b * E_;
        int rcv = e / (N_ - 1), jj = e - rcv * (N_ - 1);
        int snd = jj + (jj >= rcv ? 1 : 0);
        pr = A + (size_t)(b * N_ + rcv) * H_;
        ps = A + (size_t)(b * N_ + snd) * H_;
        if (MODE == MODE_E3) px = Aux + (size_t)m * H_;
    }

    auto ldA = [&](int k0) -> float4 {
        const int k = k0 + a_k;
        if (MODE == MODE_DIR) {
            return *(const float4*)(pr + k);
        } else if (MODE == MODE_X) {
            return *(const float4*)(pr + (size_t)(k >> 2) * (N_ * D_));
        } else if (MODE == MODE_E2) {
            return (k < H_) ? *(const float4*)(pr + k)
                            : *(const float4*)(ps + (k - H_));
        } else { // MODE_E3
            if (k < H_)     return *(const float4*)(pr + k);
            if (k < 2 * H_) return *(const float4*)(ps + (k - H_));
            return *(const float4*)(px + (k - 2 * H_));
        }
    };
    auto ldB = [&](int k0) -> float4 {
        return *(const float4*)(W + (size_t)(k0 + b_k) * NOUT + n0 + b_n);
    };

    const int tx = tid & 15, ty = tid >> 4;

    // acc[i][jp] holds packed pair (col 2*jp, 2*jp+1) for row i
    u64 acc[8][4];
#pragma unroll
    for (int i = 0; i < 8; i++)
#pragma unroll
        for (int j = 0; j < 4; j++) acc[i][j] = 0ull;

    constexpr int S = K / TK;

    // stage 0 fill
    {
        float4 ra = ldA(0), rb = ldB(0);
        sA[0][a_k + 0][a_m] = ra.x;
        sA[0][a_k + 1][a_m] = ra.y;
        sA[0][a_k + 2][a_m] = ra.z;
        sA[0][a_k + 3][a_m] = ra.w;
        *(float4*)&sB[0][b_k][b_n] = rb;
    }
    __syncthreads();

    for (int s = 0; s < S; ++s) {
        const int cur = s & 1;
        float4 na, nb;
        if (s + 1 < S) { na = ldA((s + 1) * TK); nb = ldB((s + 1) * TK); }
#pragma unroll
        for (int k = 0; k < TK; ++k) {
            float4 a0 = *(const float4*)&sA[cur][k][ty * 8];
            float4 a1 = *(const float4*)&sA[cur][k][ty * 8 + 4];
            // sB is contiguous fp32 pairs -> reinterpret as packed f32x2 (little-endian: lo=first)
            ulonglong2 bq0 = *(const ulonglong2*)&sB[cur][k][tx * 8];
            ulonglong2 bq1 = *(const ulonglong2*)&sB[cur][k][tx * 8 + 4];
            u64 bv[4] = {bq0.x, bq0.y, bq1.x, bq1.y};
            float av[8] = {a0.x, a0.y, a0.z, a0.w, a1.x, a1.y, a1.z, a1.w};
#pragma unroll
            for (int i = 0; i < 8; i++) {
                u64 ap = pk2(av[i], av[i]);
#pragma unroll
                for (int j = 0; j < 4; j++)
                    fma2(acc[i][j], ap, bv[j]);
            }
        }
        if (s + 1 < S) {
            const int nxt = cur ^ 1;
            sA[nxt][a_k + 0][a_m] = na.x;
            sA[nxt][a_k + 1][a_m] = na.y;
            sA[nxt][a_k + 2][a_m] = na.z;
            sA[nxt][a_k + 3][a_m] = na.w;
            *(float4*)&sB[nxt][b_k][b_n] = nb;
        }
        __syncthreads();
    }

    // epilogue: bias (+relu), vectorized store
    float bb[8];
#pragma unroll
    for (int j = 0; j < 8; j++) bb[j] = bias[n0 + tx * 8 + j];
#pragma unroll
    for (int i = 0; i < 8; i++) {
        float v[8];
#pragma unroll
        for (int j = 0; j < 4; j++) {
            float lo, hi;
            unpk2(lo, hi, acc[i][j]);
            float t0 = lo + bb[2 * j];
            float t1 = hi + bb[2 * j + 1];
            v[2 * j]     = RELU ? fmaxf(t0, 0.f) : t0;
            v[2 * j + 1] = RELU ? fmaxf(t1, 0.f) : t1;
        }
        float* crow = C + (size_t)(m0 + ty * 8 + i) * NOUT + n0 + tx * 8;
        float4 o0 = {v[0], v[1], v[2], v[3]};
        float4 o1 = {v[4], v[5], v[6], v[7]};
        *(float4*)(crow)     = o0;
        *(float4*)(crow + 4) = o1;
    }
}

// v[b,n,:] = sum over the 99 contiguous edges with recv==n, / N
__global__ void agg_kernel(const float* __restrict__ e, float* __restrict__ v)
{
    const int bn = blockIdx.x;               // 0..B*N-1
    const int b  = bn / N_, n = bn - b * N_;
    const int c  = threadIdx.x;              // 0..255
    const float* base = e + ((size_t)b * E_ + (size_t)n * (N_ - 1)) * H_ + c;
    float s = 0.f;
#pragma unroll 9
    for (int k = 0; k < N_ - 1; ++k) s += base[(size_t)k * H_];
    v[(size_t)bn * H_ + c] = s * (1.0f / N_);
}

// out[m,0:4] = e2[m,:] @ wo + bo ; 32 rows per block, 128 threads
__global__ __launch_bounds__(128)
void out_kernel(const float* __restrict__ e2, const float* __restrict__ wo,
                const float* __restrict__ bo, float* __restrict__ out)
{
    __shared__ float sE[32][260];
    __shared__ float sW[H_ * 4];
    const int tid = threadIdx.x;
    const size_t row0 = (size_t)blockIdx.x * 32;

    for (int i = tid; i < H_ * 4; i += 128) sW[i] = wo[i];
    for (int i = tid; i < 32 * 64; i += 128) {
        int r = i >> 6, c4 = (i & 63) << 2;
        float4 t = *(const float4*)(e2 + (row0 + r) * H_ + c4);
        *(float4*)&sE[r][c4] = t;
    }
    __syncthreads();

    const int r = tid >> 2, j = tid & 3;
    float s = bo[j];
#pragma unroll 8
    for (int k = 0; k < H_; ++k) s = fmaf(sE[r][k], sW[k * 4 + j], s);
    out[(row0 + r) * 4 + j] = s;
}

extern "C" void kernel_launch(void* const* d_in, const int* in_sizes, int n_in,
                              void* d_out, int out_size)
{
    (void)in_sizes; (void)n_in; (void)out_size;
    const float* x   = (const float*)d_in[0];
    // d_in[1]=rec, d_in[2]=send : one-hot matrices, replaced by analytic indices
    const float* w1a = (const float*)d_in[3];
    const float* b1a = (const float*)d_in[4];
    const float* w1b = (const float*)d_in[5];
    const float* b1b = (const float*)d_in[6];
    const float* w2a = (const float*)d_in[7];
    const float* b2a = (const float*)d_in[8];
    const float* w2b = (const float*)d_in[9];
    const float* b2b = (const float*)d_in[10];
    const float* w3a = (const float*)d_in[11];
    const float* b3a = (const float*)d_in[12];
    const float* w3b = (const float*)d_in[13];
    const float* b3b = (const float*)d_in[14];
    const float* w4a = (const float*)d_in[15];
    const float* b4a = (const float*)d_in[16];
    const float* w4b = (const float*)d_in[17];
    const float* b4b = (const float*)d_in[18];
    const float* wo  = (const float*)d_in[19];
    const float* bo  = (const float*)d_in[20];
    float* out = (float*)d_out;

    float *ehid, *xskip, *nodeA, *nodeB;
    cudaGetSymbolAddress((void**)&ehid,  g_ehid);
    cudaGetSymbolAddress((void**)&xskip, g_xskip);
    cudaGetSymbolAddress((void**)&nodeA, g_nodeA);
    cudaGetSymbolAddress((void**)&nodeB, g_nodeB);

    const dim3 blk(256);
    const dim3 gNode(25, 2);     // 3200/128 x 256/128
    const dim3 gEdge(2475, 2);   // 316800/128 x 256/128

    // MLP1 on nodes: x(transposed gather) -> nodeA(hidden,relu) -> nodeB(h)
    gemm_k<MODE_X,  NIN_, H_, true ><<<gNode, blk>>>(x,     nullptr, w1a, b1a, nodeA);
    gemm_k<MODE_DIR, H_,  H_, false><<<gNode, blk>>>(nodeA, nullptr, w1b, b1b, nodeB);

    // MLP2 on edges: concat(h[recv],h[send]) -> ehid(relu) -> xskip (=x_skip)
    gemm_k<MODE_E2, 2*H_, H_, true ><<<gEdge, blk>>>(nodeB, nullptr, w2a, b2a, ehid);
    gemm_k<MODE_DIR, H_,  H_, false><<<gEdge, blk>>>(ehid,  nullptr, w2b, b2b, xskip);

    // Aggregate edges->nodes: nodeA = segsum(xskip)/N
    agg_kernel<<<B_ * N_, 256>>>(xskip, nodeA);

    // MLP3 on nodes: nodeA -> nodeB(hidden,relu) -> nodeA (=v)
    gemm_k<MODE_DIR, H_, H_, true ><<<gNode, blk>>>(nodeA, nullptr, w3a, b3a, nodeB);
    gemm_k<MODE_DIR, H_, H_, false><<<gNode, blk>>>(nodeB, nullptr, w3b, b3b, nodeA);

    // MLP4 on edges: concat(v[recv],v[send],x_skip) -> ehid(relu) -> xskip (=e2)
    gemm_k<MODE_E3, 3*H_, H_, true ><<<gEdge, blk>>>(nodeA, xskip, w4a, b4a, ehid);
    gemm_k<MODE_DIR, H_,  H_, false><<<gEdge, blk>>>(ehid,  nullptr, w4b, b4b, xskip);

    // Output head: e2 @ wo + bo
    out_kernel<<<BE_ / 32, 128>>>(xskip, wo, bo, out);
}

// round 4
// speedup vs baseline: 1.7704x; 1.6824x over previous
#include <cuda_runtime.h>
#include <cstdint>

// Problem dims
#define B_   32
#define T_   50
#define N_   100
#define D_   4
#define E_   9900          // N*(N-1)
#define BE_  316800        // B*E
#define H_   256           // hidden
#define NIN_ 200           // T*D

// Scratch (device globals; no allocation allowed)
__device__ float g_ehid [BE_ * H_];       // 324 MB
__device__ float g_xskip[BE_ * H_];       // 324 MB
__device__ float g_nodeA[B_ * N_ * H_];   // 3.3 MB
__device__ float g_nodeB[B_ * N_ * H_];   // 3.3 MB
__device__ float g_wth  [1792 * 256];     // frag-ordered tf32-hi weights: w2a|w2b|w4a|w4b
__device__ float g_wtl  [1792 * 256];     // frag-ordered tf32-lo weights

enum { MODE_DIR = 0, MODE_X = 1, MODE_E2 = 2, MODE_E3 = 3 };

typedef unsigned long long u64;

// ---------------- small PTX helpers ----------------
__device__ __forceinline__ uint32_t smem_to_u32(const void* p) {
    uint32_t a;
    asm("{ .reg .u64 t; cvta.to.shared.u64 t, %1; cvt.u32.u64 %0, t; }" : "=r"(a) : "l"(p));
    return a;
}
__device__ __forceinline__ uint32_t f2tf32(float f) {
    uint32_t r; asm("cvt.rna.tf32.f32 %0, %1;" : "=r"(r) : "f"(f)); return r;
}
__device__ __forceinline__ uint4 cvt4(float4 v) {
    uint4 r; r.x = f2tf32(v.x); r.y = f2tf32(v.y); r.z = f2tf32(v.z); r.w = f2tf32(v.w);
    return r;
}
__device__ __forceinline__ void cp16(uint32_t s, const void* g) {
    asm volatile("cp.async.cg.shared.global [%0], [%1], 16;" :: "r"(s), "l"(g) : "memory");
}
__device__ __forceinline__ void cp_commit() { asm volatile("cp.async.commit_group;" ::: "memory"); }
__device__ __forceinline__ void cp_wait0()  { asm volatile("cp.async.wait_group 0;" ::: "memory"); }

__device__ __forceinline__ void mma_tf32(float* c, const uint32_t* a, uint32_t b0, uint32_t b1) {
    asm volatile(
        "mma.sync.aligned.m16n8k8.row.col.f32.tf32.tf32.f32 "
        "{%0,%1,%2,%3}, {%4,%5,%6,%7}, {%8,%9}, {%0,%1,%2,%3};"
        : "+f"(c[0]), "+f"(c[1]), "+f"(c[2]), "+f"(c[3])
        : "r"(a[0]), "r"(a[1]), "r"(a[2]), "r"(a[3]), "r"(b0), "r"(b1));
}

// ---------------- tensor-core edge GEMM (mma.sync tf32, split weights) ----------------
// C[M,256] = act(gather_A[M,K] @ W[K,256] + bias), W pre-split hi/lo tf32, frag-ordered.
// Block: 128(M) x 128(N), 256 threads = 8 warps as 4(M) x 2(N); warp tile 32x64.
//
// smem bytes: A[2] row-major padded 128x36 fl = 18432 each;
//             Bhi[2] 16384 each; Blo[2] 16384 each. total 102400.
#define SM_A(p)  ((p) * 18432u)
#define SM_BH(p) (36864u + (p) * 16384u)
#define SM_BL(p) (69632u + (p) * 16384u)
#define SMEM_MMA_BYTES 102400

template<int MODE, int K, bool RELU>
__global__ __launch_bounds__(256)
void mma_gemm(const float* __restrict__ A, const float* __restrict__ Aux,
              const float* __restrict__ Wh, const float* __restrict__ Wl,
              const float* __restrict__ bias, float* __restrict__ C)
{
    extern __shared__ char smem[];
    const uint32_t sbase = smem_to_u32(smem);
    const int tid = threadIdx.x;
    const int m0 = blockIdx.x * 128;
    const int n0 = blockIdx.y * 128;
    constexpr int S = K / 32;

    // ---- A gather setup: thread stages row arow, k-half khalf (16 floats) ----
    const int arow  = tid >> 1;
    const int khalf = (tid & 1) << 4;
    const int m = m0 + arow;
    const float* pr = nullptr; const float* ps = nullptr; const float* px = nullptr;
    if (MODE == MODE_DIR) {
        pr = A + (size_t)m * K;
    } else {
        int b = m / E_, e = m - b * E_;
        int rcv = e / (N_ - 1), jj = e - rcv * (N_ - 1);
        int snd = jj + (jj >= rcv ? 1 : 0);
        pr = A + (size_t)(b * N_ + rcv) * H_;
        ps = A + (size_t)(b * N_ + snd) * H_;
        if (MODE == MODE_E3) px = Aux + (size_t)m * H_;
    }
    auto ldA4 = [&](int k) -> float4 {
        if (MODE == MODE_DIR)     return *(const float4*)(pr + k);
        else if (MODE == MODE_E2) return (k < H_) ? *(const float4*)(pr + k)
                                                  : *(const float4*)(ps + k - H_);
        else {
            if (k < H_)          return *(const float4*)(pr + k);
            else if (k < 2 * H_) return *(const float4*)(ps + k - H_);
            else                 return *(const float4*)(px + k - 2 * H_);
        }
    };

    const float* whBase = Wh + (size_t)blockIdx.y * (K / 32) * 4096;
    const float* wlBase = Wl + (size_t)blockIdx.y * (K / 32) * 4096;

    auto stageB = [&](int t, int p) {
        const float* hs = whBase + (size_t)t * 4096;
        const float* ls = wlBase + (size_t)t * 4096;
        const uint32_t dh = sbase + SM_BH(p);
        const uint32_t dl = sbase + SM_BL(p);
#pragma unroll
        for (int i = 0; i < 4; ++i) {
            const int e4 = i * 256 + tid;            // float4 index within 4096-float tile
            cp16(dh + e4 * 16, hs + e4 * 4);
            cp16(dl + e4 * 16, ls + e4 * 4);
        }
    };
    auto stsA = [&](int p, const float4* ar) {
        float* dst = (float*)(smem + SM_A(p)) + arow * 36 + khalf;
#pragma unroll
        for (int j = 0; j < 4; ++j)
            *(uint4*)(dst + 4 * j) = cvt4(ar[j]);
    };

    // ---- compute setup ----
    const int wid = tid >> 5, lane = tid & 31;
    const int warp_m = wid >> 1, warp_n = wid & 1;
    const int g = lane >> 2, t4 = lane & 3;

    float acc[2][8][4];
#pragma unroll
    for (int i = 0; i < 2; i++)
#pragma unroll
        for (int j = 0; j < 8; j++)
#pragma unroll
            for (int c = 0; c < 4; c++) acc[i][j][c] = 0.f;

    // ---- prologue: stage 0 ----
    float4 areg[4];
#pragma unroll
    for (int j = 0; j < 4; ++j) areg[j] = ldA4(khalf + 4 * j);
    stageB(0, 0);
    cp_commit();
    stsA(0, areg);
    cp_wait0();
    __syncthreads();

#pragma unroll 1
    for (int t = 0; t < S; ++t) {
        const int p = t & 1;
        if (t + 1 < S) {
#pragma unroll
            for (int j = 0; j < 4; ++j) areg[j] = ldA4((t + 1) * 32 + khalf + 4 * j);
            stageB(t + 1, p ^ 1);
            cp_commit();
        }
        // ---- compute stage t ----
        {
            const uint32_t* sA  = (const uint32_t*)(smem + SM_A(p));
            const uint2*    sBh = (const uint2*)(smem + SM_BH(p));
            const uint2*    sBl = (const uint2*)(smem + SM_BL(p));
#pragma unroll
            for (int kk = 0; kk < 4; ++kk) {
                uint32_t a[2][4];
#pragma unroll
                for (int mt = 0; mt < 2; ++mt) {
                    const int base = ((warp_m * 2 + mt) * 16 + g) * 36 + kk * 8 + t4;
                    a[mt][0] = sA[base];
                    a[mt][1] = sA[base + 8 * 36];
                    a[mt][2] = sA[base + 4];
                    a[mt][3] = sA[base + 8 * 36 + 4];
                }
#pragma unroll
                for (int nt = 0; nt < 8; ++nt) {
                    const int bi = ((warp_n * 8 + nt) * 4 + kk) * 32 + lane;
                    uint2 bh = sBh[bi];
                    uint2 bl = sBl[bi];
#pragma unroll
                    for (int mt = 0; mt < 2; ++mt) {
                        mma_tf32(acc[mt][nt], a[mt], bh.x, bh.y);
                        mma_tf32(acc[mt][nt], a[mt], bl.x, bl.y);
                    }
                }
            }
        }
        if (t + 1 < S) stsA(p ^ 1, areg);
        cp_wait0();
        __syncthreads();
    }

    // ---- epilogue: bias (+relu), float2 stores ----
#pragma unroll
    for (int mt = 0; mt < 2; ++mt) {
#pragma unroll
        for (int nt = 0; nt < 8; ++nt) {
            const int row = m0 + warp_m * 32 + mt * 16 + g;
            const int col = n0 + warp_n * 64 + nt * 8 + t4 * 2;
            float2 bb = *(const float2*)(bias + col);
            float v0 = acc[mt][nt][0] + bb.x;
            float v1 = acc[mt][nt][1] + bb.y;
            float v2 = acc[mt][nt][2] + bb.x;
            float v3 = acc[mt][nt][3] + bb.y;
            if (RELU) {
                v0 = fmaxf(v0, 0.f); v1 = fmaxf(v1, 0.f);
                v2 = fmaxf(v2, 0.f); v3 = fmaxf(v3, 0.f);
            }
            *(float2*)(C + (size_t)row * 256 + col)       = make_float2(v0, v1);
            *(float2*)(C + (size_t)(row + 8) * 256 + col) = make_float2(v2, v3);
        }
    }
}

// ---------------- weight split + frag-order scatter ----------------
// in: w [K][256] fp32.  out: hi/lo tf32 (as f32 bit patterns), laid out so that
// each (n-block ny, k-stage s) is a contiguous 4096-float fragment-ordered tile.
__global__ void wsplit_k(const float* __restrict__ w, float* __restrict__ oh,
                         float* __restrict__ ol, int K)
{
    const int idx = blockIdx.x * 256 + threadIdx.x;   // = k*256 + n
    const int k = idx >> 8, n = idx & 255;
    const float val = w[idx];
    const uint32_t hb = f2tf32(val);
    const float hf = __uint_as_float(hb);
    const uint32_t lb = f2tf32(val - hf);
    const int ny = n >> 7, nr = n & 127;
    const int nt = nr >> 3, gg = nr & 7;
    const int s = k >> 5, kk = (k >> 3) & 3, tt = k & 7;
    const int dst = (ny * (K >> 5) + s) * 4096
                  + ((nt * 4 + kk) * 32 + (gg * 4 + (tt & 3))) * 2 + (tt >> 2);
    oh[dst] = __uint_as_float(hb);
    ol[dst] = __uint_as_float(lb);
}

// ---------------- SIMT f32x2 GEMM (node layers) ----------------
__device__ __forceinline__ u64 pk2(float lo, float hi) {
    u64 r; asm("mov.b64 %0, {%1, %2};" : "=l"(r) : "f"(lo), "f"(hi)); return r;
}
__device__ __forceinline__ void fma2(u64& d, u64 a, u64 b) {
    asm("fma.rn.f32x2 %0, %1, %2, %0;" : "+l"(d) : "l"(a), "l"(b));
}
__device__ __forceinline__ void unpk2(float& lo, float& hi, u64 v) {
    asm("mov.b64 {%0, %1}, %2;" : "=f"(lo), "=f"(hi) : "l"(v));
}

template<int MODE, int K, int NOUT, bool RELU>
__global__ __launch_bounds__(256, 2)
void gemm_k(const float* __restrict__ A, const float* __restrict__ W,
            const float* __restrict__ bias, float* __restrict__ C)
{
    constexpr int TM = 128, TN = 128, TK = 8;
    __shared__ float sA[2][TK][TM + 4];
    __shared__ __align__(16) float sB[2][TK][TN];

    const int tid = threadIdx.x;
    const int m0 = blockIdx.x * TM, n0 = blockIdx.y * TN;
    const int a_m = tid >> 1, a_k = (tid & 1) << 2;
    const int b_k = tid >> 5, b_n = (tid & 31) << 2;

    const int m = m0 + a_m;
    const float* pr;
    if (MODE == MODE_DIR) {
        pr = A + (size_t)m * K;
    } else { // MODE_X
        int b = m / N_, n = m - b * N_;
        pr = A + (size_t)b * (T_ * N_ * D_) + (size_t)n * D_;
    }
    auto ldA = [&](int k0) -> float4 {
        const int k = k0 + a_k;
        if (MODE == MODE_DIR) return *(const float4*)(pr + k);
        return *(const float4*)(pr + (size_t)(k >> 2) * (N_ * D_));
    };
    auto ldB = [&](int k0) -> float4 {
        return *(const float4*)(W + (size_t)(k0 + b_k) * NOUT + n0 + b_n);
    };

    const int tx = tid & 15, ty = tid >> 4;
    u64 acc[8][4];
#pragma unroll
    for (int i = 0; i < 8; i++)
#pragma unroll
        for (int j = 0; j < 4; j++) acc[i][j] = 0ull;

    constexpr int S = K / TK;
    {
        float4 ra = ldA(0), rb = ldB(0);
        sA[0][a_k + 0][a_m] = ra.x; sA[0][a_k + 1][a_m] = ra.y;
        sA[0][a_k + 2][a_m] = ra.z; sA[0][a_k + 3][a_m] = ra.w;
        *(float4*)&sB[0][b_k][b_n] = rb;
    }
    __syncthreads();
    for (int s = 0; s < S; ++s) {
        const int cur = s & 1;
        float4 na, nb;
        if (s + 1 < S) { na = ldA((s + 1) * TK); nb = ldB((s + 1) * TK); }
#pragma unroll
        for (int k = 0; k < TK; ++k) {
            float4 a0 = *(const float4*)&sA[cur][k][ty * 8];
            float4 a1 = *(const float4*)&sA[cur][k][ty * 8 + 4];
            ulonglong2 bq0 = *(const ulonglong2*)&sB[cur][k][tx * 8];
            ulonglong2 bq1 = *(const ulonglong2*)&sB[cur][k][tx * 8 + 4];
            u64 bv[4] = {bq0.x, bq0.y, bq1.x, bq1.y};
            float av[8] = {a0.x, a0.y, a0.z, a0.w, a1.x, a1.y, a1.z, a1.w};
#pragma unroll
            for (int i = 0; i < 8; i++) {
                u64 ap = pk2(av[i], av[i]);
#pragma unroll
                for (int j = 0; j < 4; j++) fma2(acc[i][j], ap, bv[j]);
            }
        }
        if (s + 1 < S) {
            const int nxt = cur ^ 1;
            sA[nxt][a_k + 0][a_m] = na.x; sA[nxt][a_k + 1][a_m] = na.y;
            sA[nxt][a_k + 2][a_m] = na.z; sA[nxt][a_k + 3][a_m] = na.w;
            *(float4*)&sB[nxt][b_k][b_n] = nb;
        }
        __syncthreads();
    }
    float bb[8];
#pragma unroll
    for (int j = 0; j < 8; j++) bb[j] = bias[n0 + tx * 8 + j];
#pragma unroll
    for (int i = 0; i < 8; i++) {
        float v[8];
#pragma unroll
        for (int j = 0; j < 4; j++) {
            float lo, hi; unpk2(lo, hi, acc[i][j]);
            float t0 = lo + bb[2 * j], t1 = hi + bb[2 * j + 1];
            v[2 * j]     = RELU ? fmaxf(t0, 0.f) : t0;
            v[2 * j + 1] = RELU ? fmaxf(t1, 0.f) : t1;
        }
        float* crow = C + (size_t)(m0 + ty * 8 + i) * NOUT + n0 + tx * 8;
        *(float4*)(crow)     = make_float4(v[0], v[1], v[2], v[3]);
        *(float4*)(crow + 4) = make_float4(v[4], v[5], v[6], v[7]);
    }
}

// ---------------- aggregation + output head ----------------
__global__ void agg_kernel(const float* __restrict__ e, float* __restrict__ v)
{
    const int bn = blockIdx.x;
    const int b = bn / N_, n = bn - b * N_;
    const int c = threadIdx.x;
    const float* base = e + ((size_t)b * E_ + (size_t)n * (N_ - 1)) * H_ + c;
    float s = 0.f;
#pragma unroll 9
    for (int k = 0; k < N_ - 1; ++k) s += base[(size_t)k * H_];
    v[(size_t)bn * H_ + c] = s * (1.0f / N_);
}

__global__ __launch_bounds__(128)
void out_kernel(const float* __restrict__ e2, const float* __restrict__ wo,
                const float* __restrict__ bo, float* __restrict__ out)
{
    __shared__ float sE[32][260];
    __shared__ float sW[H_ * 4];
    const int tid = threadIdx.x;
    const size_t row0 = (size_t)blockIdx.x * 32;
    for (int i = tid; i < H_ * 4; i += 128) sW[i] = wo[i];
    for (int i = tid; i < 32 * 64; i += 128) {
        int r = i >> 6, c4 = (i & 63) << 2;
        *(float4*)&sE[r][c4] = *(const float4*)(e2 + (row0 + r) * H_ + c4);
    }
    __syncthreads();
    const int r = tid >> 2, j = tid & 3;
    float s = bo[j];
#pragma unroll 8
    for (int k = 0; k < H_; ++k) s = fmaf(sE[r][k], sW[k * 4 + j], s);
    out[(row0 + r) * 4 + j] = s;
}

// ---------------- launch ----------------
extern "C" void kernel_launch(void* const* d_in, const int* in_sizes, int n_in,
                              void* d_out, int out_size)
{
    (void)in_sizes; (void)n_in; (void)out_size;
    const float* x   = (const float*)d_in[0];
    const float* w1a = (const float*)d_in[3];
    const float* b1a = (const float*)d_in[4];
    const float* w1b = (const float*)d_in[5];
    const float* b1b = (const float*)d_in[6];
    const float* w2a = (const float*)d_in[7];
    const float* b2a = (const float*)d_in[8];
    const float* w2b = (const float*)d_in[9];
    const float* b2b = (const float*)d_in[10];
    const float* w3a = (const float*)d_in[11];
    const float* b3a = (const float*)d_in[12];
    const float* w3b = (const float*)d_in[13];
    const float* b3b = (const float*)d_in[14];
    const float* w4a = (const float*)d_in[15];
    const float* b4a = (const float*)d_in[16];
    const float* w4b = (const float*)d_in[17];
    const float* b4b = (const float*)d_in[18];
    const float* wo  = (const float*)d_in[19];
    const float* bo  = (const float*)d_in[20];
    float* out = (float*)d_out;

    float *ehid, *xskip, *nodeA, *nodeB, *wth, *wtl;
    cudaGetSymbolAddress((void**)&ehid,  g_ehid);
    cudaGetSymbolAddress((void**)&xskip, g_xskip);
    cudaGetSymbolAddress((void**)&nodeA, g_nodeA);
    cudaGetSymbolAddress((void**)&nodeB, g_nodeB);
    cudaGetSymbolAddress((void**)&wth,   g_wth);
    cudaGetSymbolAddress((void**)&wtl,   g_wtl);

    float* h2a = wth;               float* l2a = wtl;                // K=512
    float* h2b = wth + 512 * 256;   float* l2b = wtl + 512 * 256;    // K=256
    float* h4a = wth + 768 * 256;   float* l4a = wtl + 768 * 256;    // K=768
    float* h4b = wth + 1536 * 256;  float* l4b = wtl + 1536 * 256;   // K=256

    cudaFuncSetAttribute(mma_gemm<MODE_E2, 512, true >, cudaFuncAttributeMaxDynamicSharedMemorySize, SMEM_MMA_BYTES);
    cudaFuncSetAttribute(mma_gemm<MODE_DIR, 256, false>, cudaFuncAttributeMaxDynamicSharedMemorySize, SMEM_MMA_BYTES);
    cudaFuncSetAttribute(mma_gemm<MODE_E3, 768, true >, cudaFuncAttributeMaxDynamicSharedMemorySize, SMEM_MMA_BYTES);

    // split+scatter weights into tf32 hi/lo frag-ordered layout
    wsplit_k<<<512, 256>>>(w2a, h2a, l2a, 512);
    wsplit_k<<<256, 256>>>(w2b, h2b, l2b, 256);
    wsplit_k<<<768, 256>>>(w4a, h4a, l4a, 768);
    wsplit_k<<<256, 256>>>(w4b, h4b, l4b, 256);

    const dim3 blk(256);
    const dim3 gNode(25, 2);
    const dim3 gEdge(2475, 2);

    // MLP1 on nodes (SIMT fp32, exact)
    gemm_k<MODE_X,  NIN_, H_, true ><<<gNode, blk>>>(x,     w1a, b1a, nodeA);
    gemm_k<MODE_DIR, H_,  H_, false><<<gNode, blk>>>(nodeA, w1b, b1b, nodeB);

    // MLP2 on edges (tf32 mma.sync, split weights)
    mma_gemm<MODE_E2, 512, true ><<<gEdge, blk, SMEM_MMA_BYTES>>>(nodeB, nullptr, h2a, l2a, b2a, ehid);
    mma_gemm<MODE_DIR, 256, false><<<gEdge, blk, SMEM_MMA_BYTES>>>(ehid,  nullptr, h2b, l2b, b2b, xskip);

    // Aggregate edges->nodes
    agg_kernel<<<B_ * N_, 256>>>(xskip, nodeA);

    // MLP3 on nodes (SIMT fp32, exact)
    gemm_k<MODE_DIR, H_, H_, true ><<<gNode, blk>>>(nodeA, w3a, b3a, nodeB);
    gemm_k<MODE_DIR, H_, H_, false><<<gNode, blk>>>(nodeB, w3b, b3b, nodeA);

    // MLP4 on edges (tf32 mma.sync, split weights)
    mma_gemm<MODE_E3, 768, true ><<<gEdge, blk, SMEM_MMA_BYTES>>>(nodeA, xskip, h4a, l4a, b4a, ehid);
    mma_gemm<MODE_DIR, 256, false><<<gEdge, blk, SMEM_MMA_BYTES>>>(ehid,  nullptr, h4b, l4b, b4b, xskip);

    // Output head
    out_kernel<<<BE_ / 32, 128>>>(xskip, wo, bo, out);
}

// round 5
// speedup vs baseline: 2.9172x; 1.6478x over previous
#include <cuda_runtime.h>
#include <cstdint>

// Problem dims
#define B_   32
#define T_   50
#define N_   100
#define D_   4
#define E_   9900          // N*(N-1)
#define BE_  316800        // B*E
#define H_   256           // hidden
#define NIN_ 200           // T*D

// Scratch (device globals; no allocation allowed)
__device__ float g_ehid [BE_ * H_];       // 324 MB
__device__ float g_xskip[BE_ * H_];       // 324 MB
__device__ float g_nodeA[B_ * N_ * H_];   // 3.3 MB
__device__ float g_nodeB[B_ * N_ * H_];   // 3.3 MB
__device__ float g_wth  [1792 * 256];     // frag-ordered tf32 weights: w2a|w2b|w4a|w4b

enum { MODE_DIR = 0, MODE_X = 1, MODE_E2 = 2, MODE_E3 = 3 };

typedef unsigned long long u64;

// ---------------- small PTX helpers ----------------
__device__ __forceinline__ uint32_t smem_to_u32(const void* p) {
    uint32_t a;
    asm("{ .reg .u64 t; cvta.to.shared.u64 t, %1; cvt.u32.u64 %0, t; }" : "=r"(a) : "l"(p));
    return a;
}
__device__ __forceinline__ uint32_t f2tf32(float f) {
    uint32_t r; asm("cvt.rna.tf32.f32 %0, %1;" : "=r"(r) : "f"(f)); return r;
}
__device__ __forceinline__ uint4 cvt4(float4 v) {
    uint4 r; r.x = f2tf32(v.x); r.y = f2tf32(v.y); r.z = f2tf32(v.z); r.w = f2tf32(v.w);
    return r;
}
__device__ __forceinline__ void cp16(uint32_t s, const void* g) {
    asm volatile("cp.async.cg.shared.global [%0], [%1], 16;" :: "r"(s), "l"(g) : "memory");
}
__device__ __forceinline__ void cp_commit() { asm volatile("cp.async.commit_group;" ::: "memory"); }
__device__ __forceinline__ void cp_wait0()  { asm volatile("cp.async.wait_group 0;" ::: "memory"); }

__device__ __forceinline__ void mma_tf32(float* c, const uint32_t* a, uint32_t b0, uint32_t b1) {
    asm volatile(
        "mma.sync.aligned.m16n8k8.row.col.f32.tf32.tf32.f32 "
        "{%0,%1,%2,%3}, {%4,%5,%6,%7}, {%8,%9}, {%0,%1,%2,%3};"
        : "+f"(c[0]), "+f"(c[1]), "+f"(c[2]), "+f"(c[3])
        : "r"(a[0]), "r"(a[1]), "r"(a[2]), "r"(a[3]), "r"(b0), "r"(b1));
}

// ---------------- tensor-core edge GEMM (mma.sync tf32, single-tf32 weights) -------
// C[M,256] = act(gather_A[M,K] @ W[K,256] + bias), W pre-rounded tf32, frag-ordered.
// Block: 128(M) x 128(N), 256 threads = 8 warps as 4(M) x 2(N); warp tile 32x64.
//
// smem bytes: A[2] row-major padded 128x36 fl = 18432 each; B[2] 16384 each.
// total 69632 -> 2 CTAs/SM.
#define SM_A(p)  ((p) * 18432u)
#define SM_B(p)  (36864u + (p) * 16384u)
#define SMEM_MMA_BYTES 69632

template<int MODE, int K, bool RELU>
__global__ __launch_bounds__(256, 2)
void mma_gemm(const float* __restrict__ A, const float* __restrict__ Aux,
              const float* __restrict__ Wh,
              const float* __restrict__ bias, float* __restrict__ C)
{
    extern __shared__ char smem[];
    const uint32_t sbase = smem_to_u32(smem);
    const int tid = threadIdx.x;
    const int m0 = blockIdx.x * 128;
    const int n0 = blockIdx.y * 128;
    constexpr int S = K / 32;

    // ---- A gather setup: thread stages row arow, k-half khalf (16 floats) ----
    const int arow  = tid >> 1;
    const int khalf = (tid & 1) << 4;
    const int m = m0 + arow;
    const float* pr = nullptr; const float* ps = nullptr; const float* px = nullptr;
    if (MODE == MODE_DIR) {
        pr = A + (size_t)m * K;
    } else {
        int b = m / E_, e = m - b * E_;
        int rcv = e / (N_ - 1), jj = e - rcv * (N_ - 1);
        int snd = jj + (jj >= rcv ? 1 : 0);
        pr = A + (size_t)(b * N_ + rcv) * H_;
        ps = A + (size_t)(b * N_ + snd) * H_;
        if (MODE == MODE_E3) px = Aux + (size_t)m * H_;
    }
    auto ldA4 = [&](int k) -> float4 {
        if (MODE == MODE_DIR)     return *(const float4*)(pr + k);
        else if (MODE == MODE_E2) return (k < H_) ? *(const float4*)(pr + k)
                                                  : *(const float4*)(ps + k - H_);
        else {
            if (k < H_)          return *(const float4*)(pr + k);
            else if (k < 2 * H_) return *(const float4*)(ps + k - H_);
            else                 return *(const float4*)(px + k - 2 * H_);
        }
    };

    const float* whBase = Wh + (size_t)blockIdx.y * (K / 32) * 4096;

    auto stageB = [&](int t, int p) {
        const float* hs = whBase + (size_t)t * 4096;
        const uint32_t dh = sbase + SM_B(p);
#pragma unroll
        for (int i = 0; i < 4; ++i) {
            const int e4 = i * 256 + tid;            // float4 index within 4096-float tile
            cp16(dh + e4 * 16, hs + e4 * 4);
        }
    };
    auto stsA = [&](int p, const float4* ar) {
        float* dst = (float*)(smem + SM_A(p)) + arow * 36 + khalf;
#pragma unroll
        for (int j = 0; j < 4; ++j)
            *(uint4*)(dst + 4 * j) = cvt4(ar[j]);
    };

    // ---- compute setup ----
    const int wid = tid >> 5, lane = tid & 31;
    const int warp_m = wid >> 1, warp_n = wid & 1;
    const int g = lane >> 2, t4 = lane & 3;

    float acc[2][8][4];
#pragma unroll
    for (int i = 0; i < 2; i++)
#pragma unroll
        for (int j = 0; j < 8; j++)
#pragma unroll
            for (int c = 0; c < 4; c++) acc[i][j][c] = 0.f;

    // ---- prologue: stage 0 ----
    float4 areg[4];
#pragma unroll
    for (int j = 0; j < 4; ++j) areg[j] = ldA4(khalf + 4 * j);
    stageB(0, 0);
    cp_commit();
    stsA(0, areg);
    cp_wait0();
    __syncthreads();

#pragma unroll 1
    for (int t = 0; t < S; ++t) {
        const int p = t & 1;
        if (t + 1 < S) {
#pragma unroll
            for (int j = 0; j < 4; ++j) areg[j] = ldA4((t + 1) * 32 + khalf + 4 * j);
            stageB(t + 1, p ^ 1);
            cp_commit();
        }
        // ---- compute stage t ----
        {
            const uint32_t* sA = (const uint32_t*)(smem + SM_A(p));
            const uint2*    sB = (const uint2*)(smem + SM_B(p));
#pragma unroll
            for (int kk = 0; kk < 4; ++kk) {
                uint32_t a[2][4];
#pragma unroll
                for (int mt = 0; mt < 2; ++mt) {
                    const int base = ((warp_m * 2 + mt) * 16 + g) * 36 + kk * 8 + t4;
                    a[mt][0] = sA[base];
                    a[mt][1] = sA[base + 8 * 36];
                    a[mt][2] = sA[base + 4];
                    a[mt][3] = sA[base + 8 * 36 + 4];
                }
#pragma unroll
                for (int nt = 0; nt < 8; ++nt) {
                    const int bi = ((warp_n * 8 + nt) * 4 + kk) * 32 + lane;
                    uint2 bh = sB[bi];
#pragma unroll
                    for (int mt = 0; mt < 2; ++mt)
                        mma_tf32(acc[mt][nt], a[mt], bh.x, bh.y);
                }
            }
        }
        if (t + 1 < S) stsA(p ^ 1, areg);
        cp_wait0();
        __syncthreads();
    }

    // ---- epilogue: bias (+relu), float2 stores ----
#pragma unroll
    for (int mt = 0; mt < 2; ++mt) {
#pragma unroll
        for (int nt = 0; nt < 8; ++nt) {
            const int row = m0 + warp_m * 32 + mt * 16 + g;
            const int col = n0 + warp_n * 64 + nt * 8 + t4 * 2;
            float2 bb = *(const float2*)(bias + col);
            float v0 = acc[mt][nt][0] + bb.x;
            float v1 = acc[mt][nt][1] + bb.y;
            float v2 = acc[mt][nt][2] + bb.x;
            float v3 = acc[mt][nt][3] + bb.y;
            if (RELU) {
                v0 = fmaxf(v0, 0.f); v1 = fmaxf(v1, 0.f);
                v2 = fmaxf(v2, 0.f); v3 = fmaxf(v3, 0.f);
            }
            *(float2*)(C + (size_t)row * 256 + col)       = make_float2(v0, v1);
            *(float2*)(C + (size_t)(row + 8) * 256 + col) = make_float2(v2, v3);
        }
    }
}

// ---------------- weight tf32-round + frag-order scatter ----------------
// in: w [K][256] fp32. out: tf32 (f32 bit patterns), (ny, k-stage) contiguous
// 4096-float fragment-ordered tiles.
__global__ void wsplit_k(const float* __restrict__ w, float* __restrict__ oh, int K)
{
    const int idx = blockIdx.x * 256 + threadIdx.x;   // = k*256 + n
    const int k = idx >> 8, n = idx & 255;
    const uint32_t hb = f2tf32(w[idx]);
    const int ny = n >> 7, nr = n & 127;
    const int nt = nr >> 3, gg = nr & 7;
    const int s = k >> 5, kk = (k >> 3) & 3, tt = k & 7;
    const int dst = (ny * (K >> 5) + s) * 4096
                  + ((nt * 4 + kk) * 32 + (gg * 4 + (tt & 3))) * 2 + (tt >> 2);
    oh[dst] = __uint_as_float(hb);
}

// ---------------- SIMT f32x2 GEMM (node layers) ----------------
__device__ __forceinline__ u64 pk2(float lo, float hi) {
    u64 r; asm("mov.b64 %0, {%1, %2};" : "=l"(r) : "f"(lo), "f"(hi)); return r;
}
__device__ __forceinline__ void fma2(u64& d, u64 a, u64 b) {
    asm("fma.rn.f32x2 %0, %1, %2, %0;" : "+l"(d) : "l"(a), "l"(b));
}
__device__ __forceinline__ void unpk2(float& lo, float& hi, u64 v) {
    asm("mov.b64 {%0, %1}, %2;" : "=f"(lo), "=f"(hi) : "l"(v));
}

template<int MODE, int K, int NOUT, bool RELU>
__global__ __launch_bounds__(256, 2)
void gemm_k(const float* __restrict__ A, const float* __restrict__ W,
            const float* __restrict__ bias, float* __restrict__ C)
{
    constexpr int TM = 128, TN = 128, TK = 8;
    __shared__ float sA[2][TK][TM + 4];
    __shared__ __align__(16) float sB[2][TK][TN];

    const int tid = threadIdx.x;
    const int m0 = blockIdx.x * TM, n0 = blockIdx.y * TN;
    const int a_m = tid >> 1, a_k = (tid & 1) << 2;
    const int b_k = tid >> 5, b_n = (tid & 31) << 2;

    const int m = m0 + a_m;
    const float* pr;
    if (MODE == MODE_DIR) {
        pr = A + (size_t)m * K;
    } else { // MODE_X
        int b = m / N_, n = m - b * N_;
        pr = A + (size_t)b * (T_ * N_ * D_) + (size_t)n * D_;
    }
    auto ldA = [&](int k0) -> float4 {
        const int k = k0 + a_k;
        if (MODE == MODE_DIR) return *(const float4*)(pr + k);
        return *(const float4*)(pr + (size_t)(k >> 2) * (N_ * D_));
    };
    auto ldB = [&](int k0) -> float4 {
        return *(const float4*)(W + (size_t)(k0 + b_k) * NOUT + n0 + b_n);
    };

    const int tx = tid & 15, ty = tid >> 4;
    u64 acc[8][4];
#pragma unroll
    for (int i = 0; i < 8; i++)
#pragma unroll
        for (int j = 0; j < 4; j++) acc[i][j] = 0ull;

    constexpr int S = K / TK;
    {
        float4 ra = ldA(0), rb = ldB(0);
        sA[0][a_k + 0][a_m] = ra.x; sA[0][a_k + 1][a_m] = ra.y;
        sA[0][a_k + 2][a_m] = ra.z; sA[0][a_k + 3][a_m] = ra.w;
        *(float4*)&sB[0][b_k][b_n] = rb;
    }
    __syncthreads();
    for (int s = 0; s < S; ++s) {
        const int cur = s & 1;
        float4 na, nb;
        if (s + 1 < S) { na = ldA((s + 1) * TK); nb = ldB((s + 1) * TK); }
#pragma unroll
        for (int k = 0; k < TK; ++k) {
            float4 a0 = *(const float4*)&sA[cur][k][ty * 8];
            float4 a1 = *(const float4*)&sA[cur][k][ty * 8 + 4];
            ulonglong2 bq0 = *(const ulonglong2*)&sB[cur][k][tx * 8];
            ulonglong2 bq1 = *(const ulonglong2*)&sB[cur][k][tx * 8 + 4];
            u64 bv[4] = {bq0.x, bq0.y, bq1.x, bq1.y};
            float av[8] = {a0.x, a0.y, a0.z, a0.w, a1.x, a1.y, a1.z, a1.w};
#pragma unroll
            for (int i = 0; i < 8; i++) {
                u64 ap = pk2(av[i], av[i]);
#pragma unroll
                for (int j = 0; j < 4; j++) fma2(acc[i][j], ap, bv[j]);
            }
        }
        if (s + 1 < S) {
            const int nxt = cur ^ 1;
            sA[nxt][a_k + 0][a_m] = na.x; sA[nxt][a_k + 1][a_m] = na.y;
            sA[nxt][a_k + 2][a_m] = na.z; sA[nxt][a_k + 3][a_m] = na.w;
            *(float4*)&sB[nxt][b_k][b_n] = nb;
        }
        __syncthreads();
    }
    float bb[8];
#pragma unroll
    for (int j = 0; j < 8; j++) bb[j] = bias[n0 + tx * 8 + j];
#pragma unroll
    for (int i = 0; i < 8; i++) {
        float v[8];
#pragma unroll
        for (int j = 0; j < 4; j++) {
            float lo, hi; unpk2(lo, hi, acc[i][j]);
            float t0 = lo + bb[2 * j], t1 = hi + bb[2 * j + 1];
            v[2 * j]     = RELU ? fmaxf(t0, 0.f) : t0;
            v[2 * j + 1] = RELU ? fmaxf(t1, 0.f) : t1;
        }
        float* crow = C + (size_t)(m0 + ty * 8 + i) * NOUT + n0 + tx * 8;
        *(float4*)(crow)     = make_float4(v[0], v[1], v[2], v[3]);
        *(float4*)(crow + 4) = make_float4(v[4], v[5], v[6], v[7]);
    }
}

// ---------------- aggregation + output head ----------------
__global__ void agg_kernel(const float* __restrict__ e, float* __restrict__ v)
{
    const int bn = blockIdx.x;
    const int b = bn / N_, n = bn - b * N_;
    const int c = threadIdx.x;
    const float* base = e + ((size_t)b * E_ + (size_t)n * (N_ - 1)) * H_ + c;
    float s = 0.f;
#pragma unroll 9
    for (int k = 0; k < N_ - 1; ++k) s += base[(size_t)k * H_];
    v[(size_t)bn * H_ + c] = s * (1.0f / N_);
}

__global__ __launch_bounds__(128)
void out_kernel(const float* __restrict__ e2, const float* __restrict__ wo,
                const float* __restrict__ bo, float* __restrict__ out)
{
    __shared__ float sE[32][260];
    __shared__ float sW[H_ * 4];
    const int tid = threadIdx.x;
    const size_t row0 = (size_t)blockIdx.x * 32;
    for (int i = tid; i < H_ * 4; i += 128) sW[i] = wo[i];
    for (int i = tid; i < 32 * 64; i += 128) {
        int r = i >> 6, c4 = (i & 63) << 2;
        *(float4*)&sE[r][c4] = *(const float4*)(e2 + (row0 + r) * H_ + c4);
    }
    __syncthreads();
    const int r = tid >> 2, j = tid & 3;
    float s = bo[j];
#pragma unroll 8
    for (int k = 0; k < H_; ++k) s = fmaf(sE[r][k], sW[k * 4 + j], s);
    out[(row0 + r) * 4 + j] = s;
}

// ---------------- launch ----------------
extern "C" void kernel_launch(void* const* d_in, const int* in_sizes, int n_in,
                              void* d_out, int out_size)
{
    (void)in_sizes; (void)n_in; (void)out_size;
    const float* x   = (const float*)d_in[0];
    const float* w1a = (const float*)d_in[3];
    const float* b1a = (const float*)d_in[4];
    const float* w1b = (const float*)d_in[5];
    const float* b1b = (const float*)d_in[6];
    const float* w2a = (const float*)d_in[7];
    const float* b2a = (const float*)d_in[8];
    const float* w2b = (const float*)d_in[9];
    const float* b2b = (const float*)d_in[10];
    const float* w3a = (const float*)d_in[11];
    const float* b3a = (const float*)d_in[12];
    const float* w3b = (const float*)d_in[13];
    const float* b3b = (const float*)d_in[14];
    const float* w4a = (const float*)d_in[15];
    const float* b4a = (const float*)d_in[16];
    const float* w4b = (const float*)d_in[17];
    const float* b4b = (const float*)d_in[18];
    const float* wo  = (const float*)d_in[19];
    const float* bo  = (const float*)d_in[20];
    float* out = (float*)d_out;

    float *ehid, *xskip, *nodeA, *nodeB, *wth;
    cudaGetSymbolAddress((void**)&ehid,  g_ehid);
    cudaGetSymbolAddress((void**)&xskip, g_xskip);
    cudaGetSymbolAddress((void**)&nodeA, g_nodeA);
    cudaGetSymbolAddress((void**)&nodeB, g_nodeB);
    cudaGetSymbolAddress((void**)&wth,   g_wth);

    float* h2a = wth;               // K=512
    float* h2b = wth + 512 * 256;   // K=256
    float* h4a = wth + 768 * 256;   // K=768
    float* h4b = wth + 1536 * 256;  // K=256

    cudaFuncSetAttribute(mma_gemm<MODE_E2, 512, true >, cudaFuncAttributeMaxDynamicSharedMemorySize, SMEM_MMA_BYTES);
    cudaFuncSetAttribute(mma_gemm<MODE_DIR, 256, false>, cudaFuncAttributeMaxDynamicSharedMemorySize, SMEM_MMA_BYTES);
    cudaFuncSetAttribute(mma_gemm<MODE_E3, 768, true >, cudaFuncAttributeMaxDynamicSharedMemorySize, SMEM_MMA_BYTES);

    // round+scatter weights into tf32 frag-ordered layout
    wsplit_k<<<512, 256>>>(w2a, h2a, 512);
    wsplit_k<<<256, 256>>>(w2b, h2b, 256);
    wsplit_k<<<768, 256>>>(w4a, h4a, 768);
    wsplit_k<<<256, 256>>>(w4b, h4b, 256);

    const dim3 blk(256);
    const dim3 gNode(25, 2);
    const dim3 gEdge(2475, 2);

    // MLP1 on nodes (SIMT fp32, exact)
    gemm_k<MODE_X,  NIN_, H_, true ><<<gNode, blk>>>(x,     w1a, b1a, nodeA);
    gemm_k<MODE_DIR, H_,  H_, false><<<gNode, blk>>>(nodeA, w1b, b1b, nodeB);

    // MLP2 on edges (tf32 mma.sync)
    mma_gemm<MODE_E2, 512, true ><<<gEdge, blk, SMEM_MMA_BYTES>>>(nodeB, nullptr, h2a, b2a, ehid);
    mma_gemm<MODE_DIR, 256, false><<<gEdge, blk, SMEM_MMA_BYTES>>>(ehid,  nullptr, h2b, b2b, xskip);

    // Aggregate edges->nodes
    agg_kernel<<<B_ * N_, 256>>>(xskip, nodeA);

    // MLP3 on nodes (SIMT fp32, exact)
    gemm_k<MODE_DIR, H_, H_, true ><<<gNode, blk>>>(nodeA, w3a, b3a, nodeB);
    gemm_k<MODE_DIR, H_, H_, false><<<gNode, blk>>>(nodeB, w3b, b3b, nodeA);

    // MLP4 on edges (tf32 mma.sync)
    mma_gemm<MODE_E3, 768, true ><<<gEdge, blk, SMEM_MMA_BYTES>>>(nodeA, xskip, h4a, b4a, ehid);
    mma_gemm<MODE_DIR, 256, false><<<gEdge, blk, SMEM_MMA_BYTES>>>(ehid,  nullptr, h4b, b4b, xskip);

    // Output head
    out_kernel<<<BE_ / 32, 128>>>(xskip, wo, bo, out);
}

// round 6
// speedup vs baseline: 3.9426x; 1.3515x over previous
#include <cuda_runtime.h>
#include <cuda_fp16.h>
#include <cstdint>

// Problem dims
#define B_   32
#define T_   50
#define N_   100
#define D_   4
#define E_   9900          // N*(N-1)
#define BE_  316800        // B*E
#define H_   256           // hidden
#define NIN_ 200           // T*D

// Scratch (device globals; no allocation allowed)
__device__ float  g_ehid [BE_ * H_];       // 324 MB
__device__ float  g_xskip[BE_ * H_];       // 324 MB
__device__ float  g_nodeA[B_ * N_ * H_];   // 3.3 MB
__device__ float  g_nodeB[B_ * N_ * H_];   // 3.3 MB
__device__ __half g_wth  [1792 * 256];     // frag-ordered fp16 weights: w2a|w2b|w4a|w4b

enum { MODE_DIR = 0, MODE_X = 1, MODE_E2 = 2, MODE_E3 = 3 };

typedef unsigned long long u64;

// ---------------- small PTX helpers ----------------
__device__ __forceinline__ uint32_t smem_to_u32(const void* p) {
    uint32_t a;
    asm("{ .reg .u64 t; cvta.to.shared.u64 t, %1; cvt.u32.u64 %0, t; }" : "=r"(a) : "l"(p));
    return a;
}
__device__ __forceinline__ uint32_t pkh2(float x, float y) {
    __half2 h = __floats2half2_rn(x, y);
    return *(uint32_t*)&h;
}
__device__ __forceinline__ void cp16(uint32_t s, const void* g) {
    asm volatile("cp.async.cg.shared.global [%0], [%1], 16;" :: "r"(s), "l"(g) : "memory");
}
__device__ __forceinline__ void cp_commit() { asm volatile("cp.async.commit_group;" ::: "memory"); }
__device__ __forceinline__ void cp_wait0()  { asm volatile("cp.async.wait_group 0;" ::: "memory"); }

__device__ __forceinline__ void mma_f16(float* c, const uint32_t* a, uint32_t b0, uint32_t b1) {
    asm volatile(
        "mma.sync.aligned.m16n8k16.row.col.f32.f16.f16.f32 "
        "{%0,%1,%2,%3}, {%4,%5,%6,%7}, {%8,%9}, {%0,%1,%2,%3};"
        : "+f"(c[0]), "+f"(c[1]), "+f"(c[2]), "+f"(c[3])
        : "r"(a[0]), "r"(a[1]), "r"(a[2]), "r"(a[3]), "r"(b0), "r"(b1));
}

// ---------------- tensor-core edge GEMM (mma.sync fp16, f32 accum) ----------------
// C[M,256] = act(gather_A[M,K] @ W[K,256] + bias), W pre-converted fp16, frag-ordered.
// Block: 128(M) x 128(N), 256 threads = 8 warps as 4(M) x 2(N); warp tile 32x64.
//
// smem: A[2] half rows, b32-stride 20 (128x20 b32 = 10240 B each);
//       B[2] frag-ordered 4096 halves = 8192 B each. total 36864 B.
#define SM_A(p)  ((p) * 10240u)
#define SM_B(p)  (20480u + (p) * 8192u)
#define SMEM_MMA_BYTES 36864

template<int MODE, int K, bool RELU>
__global__ __launch_bounds__(256, 2)
void mma_gemm(const float* __restrict__ A, const float* __restrict__ Aux,
              const __half* __restrict__ Wh,
              const float* __restrict__ bias, float* __restrict__ C)
{
    extern __shared__ char smem[];
    const uint32_t sbase = smem_to_u32(smem);
    const int tid = threadIdx.x;
    const int m0 = blockIdx.x * 128;
    const int n0 = blockIdx.y * 128;
    constexpr int S = K / 32;

    // ---- A gather setup: thread stages row arow, k-half khalf (16 floats) ----
    const int arow  = tid >> 1;
    const int khalf = (tid & 1) << 4;
    const int m = m0 + arow;
    const float* pr = nullptr; const float* ps = nullptr; const float* px = nullptr;
    if (MODE == MODE_DIR) {
        pr = A + (size_t)m * K;
    } else {
        int b = m / E_, e = m - b * E_;
        int rcv = e / (N_ - 1), jj = e - rcv * (N_ - 1);
        int snd = jj + (jj >= rcv ? 1 : 0);
        pr = A + (size_t)(b * N_ + rcv) * H_;
        ps = A + (size_t)(b * N_ + snd) * H_;
        if (MODE == MODE_E3) px = Aux + (size_t)m * H_;
    }
    auto ldA4 = [&](int k) -> float4 {
        if (MODE == MODE_DIR)     return *(const float4*)(pr + k);
        else if (MODE == MODE_E2) return (k < H_) ? *(const float4*)(pr + k)
                                                  : *(const float4*)(ps + k - H_);
        else {
            if (k < H_)          return *(const float4*)(pr + k);
            else if (k < 2 * H_) return *(const float4*)(ps + k - H_);
            else                 return *(const float4*)(px + k - 2 * H_);
        }
    };

    const __half* whBase = Wh + (size_t)blockIdx.y * (K / 32) * 4096;

    auto stageB = [&](int t, int p) {
        const char* hs = (const char*)(whBase + (size_t)t * 4096);
        const uint32_t dh = sbase + SM_B(p);
#pragma unroll
        for (int i = 0; i < 2; ++i) {
            const int e4 = i * 256 + tid;            // 16B chunk index within 8192-B tile
            cp16(dh + e4 * 16, hs + e4 * 16);
        }
    };
    auto stsA = [&](int p, const float4* ar) {
        uint32_t* dst = (uint32_t*)(smem + SM_A(p)) + arow * 20 + (tid & 1) * 8;
#pragma unroll
        for (int j = 0; j < 4; ++j) {
            dst[j * 2]     = pkh2(ar[j].x, ar[j].y);
            dst[j * 2 + 1] = pkh2(ar[j].z, ar[j].w);
        }
    };

    // ---- compute setup ----
    const int wid = tid >> 5, lane = tid & 31;
    const int warp_m = wid >> 1, warp_n = wid & 1;
    const int g = lane >> 2, t4 = lane & 3;

    float acc[2][8][4];
#pragma unroll
    for (int i = 0; i < 2; i++)
#pragma unroll
        for (int j = 0; j < 8; j++)
#pragma unroll
            for (int c = 0; c < 4; c++) acc[i][j][c] = 0.f;

    // ---- prologue: stage 0 ----
    float4 areg[4];
#pragma unroll
    for (int j = 0; j < 4; ++j) areg[j] = ldA4(khalf + 4 * j);
    stageB(0, 0);
    cp_commit();
    stsA(0, areg);
    cp_wait0();
    __syncthreads();

#pragma unroll 1
    for (int t = 0; t < S; ++t) {
        const int p = t & 1;
        if (t + 1 < S) {
#pragma unroll
            for (int j = 0; j < 4; ++j) areg[j] = ldA4((t + 1) * 32 + khalf + 4 * j);
            stageB(t + 1, p ^ 1);
            cp_commit();
        }
        // ---- compute stage t (32 k = 2 x k16) ----
        {
            const uint32_t* sA = (const uint32_t*)(smem + SM_A(p));   // b32, row stride 20
            const uint2*    sB = (const uint2*)(smem + SM_B(p));
#pragma unroll
            for (int kk = 0; kk < 2; ++kk) {
                uint32_t a[2][4];
#pragma unroll
                for (int mt = 0; mt < 2; ++mt) {
                    const int base = ((warp_m * 2 + mt) * 16 + g) * 20 + kk * 8 + t4;
                    a[mt][0] = sA[base];
                    a[mt][1] = sA[base + 8 * 20];
                    a[mt][2] = sA[base + 4];
                    a[mt][3] = sA[base + 8 * 20 + 4];
                }
#pragma unroll
                for (int nt = 0; nt < 8; ++nt) {
                    const int bi = ((warp_n * 8 + nt) * 2 + kk) * 32 + lane;
                    uint2 b = sB[bi];
#pragma unroll
                    for (int mt = 0; mt < 2; ++mt)
                        mma_f16(acc[mt][nt], a[mt], b.x, b.y);
                }
            }
        }
        if (t + 1 < S) stsA(p ^ 1, areg);
        cp_wait0();
        __syncthreads();
    }

    // ---- epilogue: bias (+relu), float2 stores ----
#pragma unroll
    for (int mt = 0; mt < 2; ++mt) {
#pragma unroll
        for (int nt = 0; nt < 8; ++nt) {
            const int row = m0 + warp_m * 32 + mt * 16 + g;
            const int col = n0 + warp_n * 64 + nt * 8 + t4 * 2;
            float2 bb = *(const float2*)(bias + col);
            float v0 = acc[mt][nt][0] + bb.x;
            float v1 = acc[mt][nt][1] + bb.y;
            float v2 = acc[mt][nt][2] + bb.x;
            float v3 = acc[mt][nt][3] + bb.y;
            if (RELU) {
                v0 = fmaxf(v0, 0.f); v1 = fmaxf(v1, 0.f);
                v2 = fmaxf(v2, 0.f); v3 = fmaxf(v3, 0.f);
            }
            *(float2*)(C + (size_t)row * 256 + col)       = make_float2(v0, v1);
            *(float2*)(C + (size_t)(row + 8) * 256 + col) = make_float2(v2, v3);
        }
    }
}

// ---------------- weight fp16-convert + frag-order scatter ----------------
// in: w [K][256] fp32. out: fp16 halves laid out so each (ny, k-stage) is a
// contiguous 4096-half fragment-ordered tile matching the m16n8k16 B fragment:
// lane = g*4+t4 holds rows {2t4,2t4+1,2t4+8,2t4+9} of col g (per n8 group, k16 step).
__global__ void wsplit_k(const float* __restrict__ w, __half* __restrict__ oh, int K)
{
    const int idx = blockIdx.x * 256 + threadIdx.x;   // = k*256 + n
    const int k = idx >> 8, n = idx & 255;
    const __half hv = __float2half_rn(w[idx]);
    const int ny = n >> 7, nr = n & 127;
    const int nt = nr >> 3, gg = nr & 7;
    const int s = k >> 5, kr = k & 31;
    const int kk = kr >> 4, kr16 = kr & 15;
    const int reg = (kr16 >= 8) ? 1 : 0;
    const int t4 = (kr16 & 7) >> 1;
    const int hp = kr16 & 1;
    const int lane = gg * 4 + t4;
    const int tile = ny * (K >> 5) + s;
    const int dst = tile * 4096 + ((nt * 2 + kk) * 32 + lane) * 4 + reg * 2 + hp;
    oh[dst] = hv;
}

// ---------------- SIMT f32x2 GEMM (node layers) ----------------
__device__ __forceinline__ u64 pk2(float lo, float hi) {
    u64 r; asm("mov.b64 %0, {%1, %2};" : "=l"(r) : "f"(lo), "f"(hi)); return r;
}
__device__ __forceinline__ void fma2(u64& d, u64 a, u64 b) {
    asm("fma.rn.f32x2 %0, %1, %2, %0;" : "+l"(d) : "l"(a), "l"(b));
}
__device__ __forceinline__ void unpk2(float& lo, float& hi, u64 v) {
    asm("mov.b64 {%0, %1}, %2;" : "=f"(lo), "=f"(hi) : "l"(v));
}

template<int MODE, int K, int NOUT, bool RELU>
__global__ __launch_bounds__(256, 2)
void gemm_k(const float* __restrict__ A, const float* __restrict__ W,
            const float* __restrict__ bias, float* __restrict__ C)
{
    constexpr int TM = 128, TN = 128, TK = 8;
    __shared__ float sA[2][TK][TM + 4];
    __shared__ __align__(16) float sB[2][TK][TN];

    const int tid = threadIdx.x;
    const int m0 = blockIdx.x * TM, n0 = blockIdx.y * TN;
    const int a_m = tid >> 1, a_k = (tid & 1) << 2;
    const int b_k = tid >> 5, b_n = (tid & 31) << 2;

    const int m = m0 + a_m;
    const float* pr;
    if (MODE == MODE_DIR) {
        pr = A + (size_t)m * K;
    } else { // MODE_X
        int b = m / N_, n = m - b * N_;
        pr = A + (size_t)b * (T_ * N_ * D_) + (size_t)n * D_;
    }
    auto ldA = [&](int k0) -> float4 {
        const int k = k0 + a_k;
        if (MODE == MODE_DIR) return *(const float4*)(pr + k);
        return *(const float4*)(pr + (size_t)(k >> 2) * (N_ * D_));
    };
    auto ldB = [&](int k0) -> float4 {
        return *(const float4*)(W + (size_t)(k0 + b_k) * NOUT + n0 + b_n);
    };

    const int tx = tid & 15, ty = tid >> 4;
    u64 acc[8][4];
#pragma unroll
    for (int i = 0; i < 8; i++)
#pragma unroll
        for (int j = 0; j < 4; j++) acc[i][j] = 0ull;

    constexpr int S = K / TK;
    {
        float4 ra = ldA(0), rb = ldB(0);
        sA[0][a_k + 0][a_m] = ra.x; sA[0][a_k + 1][a_m] = ra.y;
        sA[0][a_k + 2][a_m] = ra.z; sA[0][a_k + 3][a_m] = ra.w;
        *(float4*)&sB[0][b_k][b_n] = rb;
    }
    __syncthreads();
    for (int s = 0; s < S; ++s) {
        const int cur = s & 1;
        float4 na, nb;
        if (s + 1 < S) { na = ldA((s + 1) * TK); nb = ldB((s + 1) * TK); }
#pragma unroll
        for (int k = 0; k < TK; ++k) {
            float4 a0 = *(const float4*)&sA[cur][k][ty * 8];
            float4 a1 = *(const float4*)&sA[cur][k][ty * 8 + 4];
            ulonglong2 bq0 = *(const ulonglong2*)&sB[cur][k][tx * 8];
            ulonglong2 bq1 = *(const ulonglong2*)&sB[cur][k][tx * 8 + 4];
            u64 bv[4] = {bq0.x, bq0.y, bq1.x, bq1.y};
            float av[8] = {a0.x, a0.y, a0.z, a0.w, a1.x, a1.y, a1.z, a1.w};
#pragma unroll
            for (int i = 0; i < 8; i++) {
                u64 ap = pk2(av[i], av[i]);
#pragma unroll
                for (int j = 0; j < 4; j++) fma2(acc[i][j], ap, bv[j]);
            }
        }
        if (s + 1 < S) {
            const int nxt = cur ^ 1;
            sA[nxt][a_k + 0][a_m] = na.x; sA[nxt][a_k + 1][a_m] = na.y;
            sA[nxt][a_k + 2][a_m] = na.z; sA[nxt][a_k + 3][a_m] = na.w;
            *(float4*)&sB[nxt][b_k][b_n] = nb;
        }
        __syncthreads();
    }
    float bb[8];
#pragma unroll
    for (int j = 0; j < 8; j++) bb[j] = bias[n0 + tx * 8 + j];
#pragma unroll
    for (int i = 0; i < 8; i++) {
        float v[8];
#pragma unroll
        for (int j = 0; j < 4; j++) {
            float lo, hi; unpk2(lo, hi, acc[i][j]);
            float t0 = lo + bb[2 * j], t1 = hi + bb[2 * j + 1];
            v[2 * j]     = RELU ? fmaxf(t0, 0.f) : t0;
            v[2 * j + 1] = RELU ? fmaxf(t1, 0.f) : t1;
        }
        float* crow = C + (size_t)(m0 + ty * 8 + i) * NOUT + n0 + tx * 8;
        *(float4*)(crow)     = make_float4(v[0], v[1], v[2], v[3]);
        *(float4*)(crow + 4) = make_float4(v[4], v[5], v[6], v[7]);
    }
}

// ---------------- aggregation + output head ----------------
__global__ void agg_kernel(const float* __restrict__ e, float* __restrict__ v)
{
    const int bn = blockIdx.x;
    const int b = bn / N_, n = bn - b * N_;
    const int c = threadIdx.x;
    const float* base = e + ((size_t)b * E_ + (size_t)n * (N_ - 1)) * H_ + c;
    float s = 0.f;
#pragma unroll 9
    for (int k = 0; k < N_ - 1; ++k) s += base[(size_t)k * H_];
    v[(size_t)bn * H_ + c] = s * (1.0f / N_);
}

__global__ __launch_bounds__(128)
void out_kernel(const float* __restrict__ e2, const float* __restrict__ wo,
                const float* __restrict__ bo, float* __restrict__ out)
{
    __shared__ float sE[32][260];
    __shared__ float sW[H_ * 4];
    const int tid = threadIdx.x;
    const size_t row0 = (size_t)blockIdx.x * 32;
    for (int i = tid; i < H_ * 4; i += 128) sW[i] = wo[i];
    for (int i = tid; i < 32 * 64; i += 128) {
        int r = i >> 6, c4 = (i & 63) << 2;
        *(float4*)&sE[r][c4] = *(const float4*)(e2 + (row0 + r) * H_ + c4);
    }
    __syncthreads();
    const int r = tid >> 2, j = tid & 3;
    float s = bo[j];
#pragma unroll 8
    for (int k = 0; k < H_; ++k) s = fmaf(sE[r][k], sW[k * 4 + j], s);
    out[(row0 + r) * 4 + j] = s;
}

// ---------------- launch ----------------
extern "C" void kernel_launch(void* const* d_in, const int* in_sizes, int n_in,
                              void* d_out, int out_size)
{
    (void)in_sizes; (void)n_in; (void)out_size;
    const float* x   = (const float*)d_in[0];
    const float* w1a = (const float*)d_in[3];
    const float* b1a = (const float*)d_in[4];
    const float* w1b = (const float*)d_in[5];
    const float* b1b = (const float*)d_in[6];
    const float* w2a = (const float*)d_in[7];
    const float* b2a = (const float*)d_in[8];
    const float* w2b = (const float*)d_in[9];
    const float* b2b = (const float*)d_in[10];
    const float* w3a = (const float*)d_in[11];
    const float* b3a = (const float*)d_in[12];
    const float* w3b = (const float*)d_in[13];
    const float* b3b = (const float*)d_in[14];
    const float* w4a = (const float*)d_in[15];
    const float* b4a = (const float*)d_in[16];
    const float* w4b = (const float*)d_in[17];
    const float* b4b = (const float*)d_in[18];
    const float* wo  = (const float*)d_in[19];
    const float* bo  = (const float*)d_in[20];
    float* out = (float*)d_out;

    float *ehid, *xskip, *nodeA, *nodeB; __half* wth;
    cudaGetSymbolAddress((void**)&ehid,  g_ehid);
    cudaGetSymbolAddress((void**)&xskip, g_xskip);
    cudaGetSymbolAddress((void**)&nodeA, g_nodeA);
    cudaGetSymbolAddress((void**)&nodeB, g_nodeB);
    cudaGetSymbolAddress((void**)&wth,   g_wth);

    __half* h2a = wth;               // K=512
    __half* h2b = wth + 512 * 256;   // K=256
    __half* h4a = wth + 768 * 256;   // K=768
    __half* h4b = wth + 1536 * 256;  // K=256

    cudaFuncSetAttribute(mma_gemm<MODE_E2, 512, true >, cudaFuncAttributeMaxDynamicSharedMemorySize, SMEM_MMA_BYTES);
    cudaFuncSetAttribute(mma_gemm<MODE_DIR, 256, false>, cudaFuncAttributeMaxDynamicSharedMemorySize, SMEM_MMA_BYTES);
    cudaFuncSetAttribute(mma_gemm<MODE_E3, 768, true >, cudaFuncAttributeMaxDynamicSharedMemorySize, SMEM_MMA_BYTES);

    // convert+scatter weights into fp16 frag-ordered layout
    wsplit_k<<<512, 256>>>(w2a, h2a, 512);
    wsplit_k<<<256, 256>>>(w2b, h2b, 256);
    wsplit_k<<<768, 256>>>(w4a, h4a, 768);
    wsplit_k<<<256, 256>>>(w4b, h4b, 256);

    const dim3 blk(256);
    const dim3 gNode(25, 2);
    const dim3 gEdge(2475, 2);

    // MLP1 on nodes (SIMT fp32, exact)
    gemm_k<MODE_X,  NIN_, H_, true ><<<gNode, blk>>>(x,     w1a, b1a, nodeA);
    gemm_k<MODE_DIR, H_,  H_, false><<<gNode, blk>>>(nodeA, w1b, b1b, nodeB);

    // MLP2 on edges (fp16 mma.sync, f32 accum)
    mma_gemm<MODE_E2, 512, true ><<<gEdge, blk, SMEM_MMA_BYTES>>>(nodeB, nullptr, h2a, b2a, ehid);
    mma_gemm<MODE_DIR, 256, false><<<gEdge, blk, SMEM_MMA_BYTES>>>(ehid,  nullptr, h2b, b2b, xskip);

    // Aggregate edges->nodes
    agg_kernel<<<B_ * N_, 256>>>(xskip, nodeA);

    // MLP3 on nodes (SIMT fp32, exact)
    gemm_k<MODE_DIR, H_, H_, true ><<<gNode, blk>>>(nodeA, w3a, b3a, nodeB);
    gemm_k<MODE_DIR, H_, H_, false><<<gNode, blk>>>(nodeB, w3b, b3b, nodeA);

    // MLP4 on edges (fp16 mma.sync, f32 accum)
    mma_gemm<MODE_E3, 768, true ><<<gEdge, blk, SMEM_MMA_BYTES>>>(nodeA, xskip, h4a, b4a, ehid);
    mma_gemm<MODE_DIR, 256, false><<<gEdge, blk, SMEM_MMA_BYTES>>>(ehid,  nullptr, h4b, b4b, xskip);

    // Output head
    out_kernel<<<BE_ / 32, 128>>>(xskip, wo, bo, out);
}

// round 7
// speedup vs baseline: 4.7511x; 1.2051x over previous
#include <cuda_runtime.h>
#include <cuda_fp16.h>
#include <cstdint>

// Problem dims
#define B_   32
#define T_   50
#define N_   100
#define D_   4
#define E_   9900          // N*(N-1)
#define BE_  316800        // B*E
#define H_   256           // hidden
#define NIN_ 200           // T*D

// Scratch (device globals; no allocation allowed)
__device__ float  g_ehid [BE_ * H_];       // used as __half e2 buffer
__device__ float  g_xskip[BE_ * H_];       // used as __half x_skip buffer
__device__ float  g_nodeA[B_ * N_ * H_];   // 3.3 MB
__device__ float  g_nodeB[B_ * N_ * H_];   // 3.3 MB
__device__ __half g_wth  [1792 * 256];     // frag-ordered fp16 weights: w2a|w2b|w4a|w4b

enum { MODE_DIR = 0, MODE_X = 1, MODE_E2 = 2, MODE_E3 = 3 };

typedef unsigned long long u64;

// ---------------- small PTX helpers ----------------
__device__ __forceinline__ uint32_t smem_to_u32(const void* p) {
    uint32_t a;
    asm("{ .reg .u64 t; cvta.to.shared.u64 t, %1; cvt.u32.u64 %0, t; }" : "=r"(a) : "l"(p));
    return a;
}
__device__ __forceinline__ uint32_t pkh2(float x, float y) {
    __half2 h = __floats2half2_rn(x, y);
    return *(uint32_t*)&h;
}
__device__ __forceinline__ void cp16(uint32_t s, const void* g) {
    asm volatile("cp.async.cg.shared.global [%0], [%1], 16;" :: "r"(s), "l"(g) : "memory");
}
__device__ __forceinline__ void cp_commit() { asm volatile("cp.async.commit_group;" ::: "memory"); }
__device__ __forceinline__ void cp_wait0()  { asm volatile("cp.async.wait_group 0;" ::: "memory"); }

__device__ __forceinline__ void mma_f16(float* c, const uint32_t* a, uint32_t b0, uint32_t b1) {
    asm volatile(
        "mma.sync.aligned.m16n8k16.row.col.f32.f16.f16.f32 "
        "{%0,%1,%2,%3}, {%4,%5,%6,%7}, {%8,%9}, {%0,%1,%2,%3};"
        : "+f"(c[0]), "+f"(c[1]), "+f"(c[2]), "+f"(c[3])
        : "r"(a[0]), "r"(a[1]), "r"(a[2]), "r"(a[3]), "r"(b0), "r"(b1));
}

// ---------------- fused edge MLP (2 GEMMs, hidden kept in smem) ----------------
// out[M,256](fp16) = (relu(gather_A[M,K1] @ W1 + b1)) @ W2 + b2
// Block: 128(M) x 256(N), 256 threads = 8 warps as 4(M) x 2(N); warp tile 32x128.
// smem: A[2] fp16 rows b32-stride 20 (10240 B each); B[2] frag tiles 16 KB each;
//       hidden 128 x 132 b32 (67584 B). total 120832 B -> 1 CTA/SM.
#define SM_A(p)  ((p) * 10240u)
#define SM_B(p)  (20480u + (p) * 16384u)
#define SM_H     (53248u)
#define SMEM_FUSED_BYTES 120832

template<int MODE, int K1>
__global__ __launch_bounds__(256, 1)
void fused_mlp(const float* __restrict__ A, const __half* __restrict__ Aux,
               const __half* __restrict__ W1, const float* __restrict__ b1v,
               const __half* __restrict__ W2, const float* __restrict__ b2v,
               __half* __restrict__ C)
{
    extern __shared__ char smem[];
    const uint32_t sbase = smem_to_u32(smem);
    const int tid = threadIdx.x;
    const int m0 = blockIdx.x * 128;
    constexpr int S1 = K1 / 32;

    // ---- A gather setup: thread stages row arow, k-half khalf (16 values) ----
    const int arow  = tid >> 1;
    const int khalf = (tid & 1) << 4;
    const int m = m0 + arow;
    const float* pr = nullptr; const float* ps = nullptr; const __half* px = nullptr;
    {
        int b = m / E_, e = m - b * E_;
        int rcv = e / (N_ - 1), jj = e - rcv * (N_ - 1);
        int snd = jj + (jj >= rcv ? 1 : 0);
        pr = A + (size_t)(b * N_ + rcv) * H_;
        ps = A + (size_t)(b * N_ + snd) * H_;
        if (MODE == MODE_E3) px = Aux + (size_t)m * H_;
    }

    uint4 ar[4];
    bool is16 = false;
    auto ldApref = [&](int kg) {           // kg = stage*32
        const int k0 = kg + khalf;
        if (MODE == MODE_E3 && k0 >= 2 * H_) {
            const uint4* s = (const uint4*)(px + (k0 - 2 * H_));
            ar[0] = s[0]; ar[1] = s[1];
            is16 = true;
        } else {
            const float* base = (k0 < H_) ? (pr + k0) : (ps + (k0 - H_));
#pragma unroll
            for (int j = 0; j < 4; ++j)
                ar[j] = *(const uint4*)(base + 4 * j);
            is16 = false;
        }
    };
    auto stsA = [&](int p) {
        uint32_t* dst = (uint32_t*)(smem + SM_A(p)) + arow * 20 + (tid & 1) * 8;
        if (is16) {
            *(uint4*)dst       = ar[0];
            *(uint4*)(dst + 4) = ar[1];
        } else {
#pragma unroll
            for (int j = 0; j < 4; ++j) {
                const float4 f = *(const float4*)&ar[j];
                dst[j * 2]     = pkh2(f.x, f.y);
                dst[j * 2 + 1] = pkh2(f.z, f.w);
            }
        }
    };
    auto stageB = [&](const __half* W, int t, int p) {
        const char* hs = (const char*)(W + (size_t)t * 8192);
        const uint32_t dh = sbase + SM_B(p);
#pragma unroll
        for (int i = 0; i < 4; ++i) {
            const int e4 = i * 256 + tid;            // 16B chunk index within 16 KB tile
            cp16(dh + e4 * 16, hs + e4 * 16);
        }
    };

    // ---- compute setup ----
    const int wid = tid >> 5, lane = tid & 31;
    const int warp_m = wid >> 1, warp_n = wid & 1;
    const int g = lane >> 2, t4 = lane & 3;

    // ================= GEMM 1 =================
    float acc[2][16][4];
#pragma unroll
    for (int i = 0; i < 2; i++)
#pragma unroll
        for (int j = 0; j < 16; j++)
#pragma unroll
            for (int c = 0; c < 4; c++) acc[i][j][c] = 0.f;

    ldApref(0);
    stageB(W1, 0, 0);
    cp_commit();
    stsA(0);
    cp_wait0();
    __syncthreads();

#pragma unroll 1
    for (int t = 0; t < S1; ++t) {
        const int p = t & 1;
        if (t + 1 < S1) {
            ldApref((t + 1) * 32);
            stageB(W1, t + 1, p ^ 1);
            cp_commit();
        }
        {
            const uint32_t* sA = (const uint32_t*)(smem + SM_A(p));   // b32, row stride 20
            const uint2*    sB = (const uint2*)(smem + SM_B(p));
#pragma unroll
            for (int kk = 0; kk < 2; ++kk) {
                uint32_t a[2][4];
#pragma unroll
                for (int mt = 0; mt < 2; ++mt) {
                    const int base = ((warp_m * 2 + mt) * 16 + g) * 20 + kk * 8 + t4;
                    a[mt][0] = sA[base];
                    a[mt][1] = sA[base + 8 * 20];
                    a[mt][2] = sA[base + 4];
                    a[mt][3] = sA[base + 8 * 20 + 4];
                }
#pragma unroll
                for (int nt = 0; nt < 16; ++nt) {
                    const int bi = warp_n * 1024 + ((nt * 2 + kk) * 32 + lane);
                    uint2 b = sB[bi];
#pragma unroll
                    for (int mt = 0; mt < 2; ++mt)
                        mma_f16(acc[mt][nt], a[mt], b.x, b.y);
                }
            }
        }
        if (t + 1 < S1) stsA(p ^ 1);
        cp_wait0();
        __syncthreads();
    }

    // epilogue 1: bias + relu -> hidden smem (fp16, b32 stride 132)
    {
        uint32_t* sH = (uint32_t*)(smem + SM_H);
#pragma unroll
        for (int mt = 0; mt < 2; ++mt) {
            const int r0 = warp_m * 32 + mt * 16 + g;
#pragma unroll
            for (int nt = 0; nt < 16; ++nt) {
                const int col = warp_n * 128 + nt * 8 + t4 * 2;
                const float2 bb = *(const float2*)(b1v + col);
                const float v0 = fmaxf(acc[mt][nt][0] + bb.x, 0.f);
                const float v1 = fmaxf(acc[mt][nt][1] + bb.y, 0.f);
                const float v2 = fmaxf(acc[mt][nt][2] + bb.x, 0.f);
                const float v3 = fmaxf(acc[mt][nt][3] + bb.y, 0.f);
                const int cb = warp_n * 64 + nt * 4 + t4;     // b32 (half2) col
                sH[r0 * 132 + cb]       = pkh2(v0, v1);
                sH[(r0 + 8) * 132 + cb] = pkh2(v2, v3);
            }
        }
    }
    // ================= GEMM 2 (K2 = 256) =================
#pragma unroll
    for (int i = 0; i < 2; i++)
#pragma unroll
        for (int j = 0; j < 16; j++)
#pragma unroll
            for (int c = 0; c < 4; c++) acc[i][j][c] = 0.f;

    stageB(W2, 0, 0);
    cp_commit();
    __syncthreads();            // hidden visible to all warps

#pragma unroll 1
    for (int t2 = 0; t2 < 8; ++t2) {
        const int p = t2 & 1;
        if (t2 + 1 < 8) { stageB(W2, t2 + 1, p ^ 1); cp_commit(); }
        cp_wait0();             // current buffer landed (prev commit) — NB: also waits new; acceptable
        __syncthreads();
        {
            const uint32_t* sH = (const uint32_t*)(smem + SM_H);
            const uint2*    sB = (const uint2*)(smem + SM_B(p));
#pragma unroll
            for (int kk = 0; kk < 2; ++kk) {
                uint32_t a[2][4];
#pragma unroll
                for (int mt = 0; mt < 2; ++mt) {
                    const int r0 = warp_m * 32 + mt * 16 + g;
                    const int cb = t2 * 16 + kk * 8 + t4;
                    a[mt][0] = sH[r0 * 132 + cb];
                    a[mt][1] = sH[(r0 + 8) * 132 + cb];
                    a[mt][2] = sH[r0 * 132 + cb + 4];
                    a[mt][3] = sH[(r0 + 8) * 132 + cb + 4];
                }
#pragma unroll
                for (int nt = 0; nt < 16; ++nt) {
                    const int bi = warp_n * 1024 + ((nt * 2 + kk) * 32 + lane);
                    uint2 b = sB[bi];
#pragma unroll
                    for (int mt = 0; mt < 2; ++mt)
                        mma_f16(acc[mt][nt], a[mt], b.x, b.y);
                }
            }
        }
        __syncthreads();
    }

    // epilogue 2: bias (no relu), fp16 stores
#pragma unroll
    for (int mt = 0; mt < 2; ++mt) {
#pragma unroll
        for (int nt = 0; nt < 16; ++nt) {
            const int row = m0 + warp_m * 32 + mt * 16 + g;
            const int col = warp_n * 128 + nt * 8 + t4 * 2;
            const float2 bb = *(const float2*)(b2v + col);
            const uint32_t h0 = pkh2(acc[mt][nt][0] + bb.x, acc[mt][nt][1] + bb.y);
            const uint32_t h1 = pkh2(acc[mt][nt][2] + bb.x, acc[mt][nt][3] + bb.y);
            *(uint32_t*)(C + (size_t)row * 256 + col)       = h0;
            *(uint32_t*)(C + (size_t)(row + 8) * 256 + col) = h1;
        }
    }
}

// ---------------- weight fp16-convert + frag-order scatter ----------------
// in: w [K][256] fp32. out: fp16, tiles ordered (k-stage s major, ny inner):
// tile (s*2+ny) is a 4096-half fragment-ordered block for n in [ny*128,(ny+1)*128).
__global__ void wsplit_k(const float* __restrict__ w, __half* __restrict__ oh, int K)
{
    const int idx = blockIdx.x * 256 + threadIdx.x;   // = k*256 + n
    const int k = idx >> 8, n = idx & 255;
    const __half hv = __float2half_rn(w[idx]);
    const int ny = n >> 7, nr = n & 127;
    const int nt = nr >> 3, gg = nr & 7;
    const int s = k >> 5, kr = k & 31;
    const int kk = kr >> 4, kr16 = kr & 15;
    const int reg = (kr16 >= 8) ? 1 : 0;
    const int t4 = (kr16 & 7) >> 1;
    const int hp = kr16 & 1;
    const int lane = gg * 4 + t4;
    const int dst = (s * 2 + ny) * 4096 + ((nt * 2 + kk) * 32 + lane) * 4 + reg * 2 + hp;
    oh[dst] = hv;
}

// ---------------- SIMT f32x2 GEMM (node layers, exact fp32) ----------------
__device__ __forceinline__ u64 pk2(float lo, float hi) {
    u64 r; asm("mov.b64 %0, {%1, %2};" : "=l"(r) : "f"(lo), "f"(hi)); return r;
}
__device__ __forceinline__ void fma2(u64& d, u64 a, u64 b) {
    asm("fma.rn.f32x2 %0, %1, %2, %0;" : "+l"(d) : "l"(a), "l"(b));
}
__device__ __forceinline__ void unpk2(float& lo, float& hi, u64 v) {
    asm("mov.b64 {%0, %1}, %2;" : "=f"(lo), "=f"(hi) : "l"(v));
}

template<int MODE, int K, int NOUT, bool RELU>
__global__ __launch_bounds__(256, 2)
void gemm_k(const float* __restrict__ A, const float* __restrict__ W,
            const float* __restrict__ bias, float* __restrict__ C)
{
    constexpr int TM = 128, TN = 128, TK = 8;
    __shared__ float sA[2][TK][TM + 4];
    __shared__ __align__(16) float sB[2][TK][TN];

    const int tid = threadIdx.x;
    const int m0 = blockIdx.x * TM, n0 = blockIdx.y * TN;
    const int a_m = tid >> 1, a_k = (tid & 1) << 2;
    const int b_k = tid >> 5, b_n = (tid & 31) << 2;

    const int m = m0 + a_m;
    const float* pr;
    if (MODE == MODE_DIR) {
        pr = A + (size_t)m * K;
    } else { // MODE_X
        int b = m / N_, n = m - b * N_;
        pr = A + (size_t)b * (T_ * N_ * D_) + (size_t)n * D_;
    }
    auto ldA = [&](int k0) -> float4 {
        const int k = k0 + a_k;
        if (MODE == MODE_DIR) return *(const float4*)(pr + k);
        return *(const float4*)(pr + (size_t)(k >> 2) * (N_ * D_));
    };
    auto ldB = [&](int k0) -> float4 {
        return *(const float4*)(W + (size_t)(k0 + b_k) * NOUT + n0 + b_n);
    };

    const int tx = tid & 15, ty = tid >> 4;
    u64 acc[8][4];
#pragma unroll
    for (int i = 0; i < 8; i++)
#pragma unroll
        for (int j = 0; j < 4; j++) acc[i][j] = 0ull;

    constexpr int S = K / TK;
    {
        float4 ra = ldA(0), rb = ldB(0);
        sA[0][a_k + 0][a_m] = ra.x; sA[0][a_k + 1][a_m] = ra.y;
        sA[0][a_k + 2][a_m] = ra.z; sA[0][a_k + 3][a_m] = ra.w;
        *(float4*)&sB[0][b_k][b_n] = rb;
    }
    __syncthreads();
    for (int s = 0; s < S; ++s) {
        const int cur = s & 1;
        float4 na, nb;
        if (s + 1 < S) { na = ldA((s + 1) * TK); nb = ldB((s + 1) * TK); }
#pragma unroll
        for (int k = 0; k < TK; ++k) {
            float4 a0 = *(const float4*)&sA[cur][k][ty * 8];
            float4 a1 = *(const float4*)&sA[cur][k][ty * 8 + 4];
            ulonglong2 bq0 = *(const ulonglong2*)&sB[cur][k][tx * 8];
            ulonglong2 bq1 = *(const ulonglong2*)&sB[cur][k][tx * 8 + 4];
            u64 bv[4] = {bq0.x, bq0.y, bq1.x, bq1.y};
            float av[8] = {a0.x, a0.y, a0.z, a0.w, a1.x, a1.y, a1.z, a1.w};
#pragma unroll
            for (int i = 0; i < 8; i++) {
                u64 ap = pk2(av[i], av[i]);
#pragma unroll
                for (int j = 0; j < 4; j++) fma2(acc[i][j], ap, bv[j]);
            }
        }
        if (s + 1 < S) {
            const int nxt = cur ^ 1;
            sA[nxt][a_k + 0][a_m] = na.x; sA[nxt][a_k + 1][a_m] = na.y;
            sA[nxt][a_k + 2][a_m] = na.z; sA[nxt][a_k + 3][a_m] = na.w;
            *(float4*)&sB[nxt][b_k][b_n] = nb;
        }
        __syncthreads();
    }
    float bb[8];
#pragma unroll
    for (int j = 0; j < 8; j++) bb[j] = bias[n0 + tx * 8 + j];
#pragma unroll
    for (int i = 0; i < 8; i++) {
        float v[8];
#pragma unroll
        for (int j = 0; j < 4; j++) {
            float lo, hi; unpk2(lo, hi, acc[i][j]);
            float t0 = lo + bb[2 * j], t1 = hi + bb[2 * j + 1];
            v[2 * j]     = RELU ? fmaxf(t0, 0.f) : t0;
            v[2 * j + 1] = RELU ? fmaxf(t1, 0.f) : t1;
        }
        float* crow = C + (size_t)(m0 + ty * 8 + i) * NOUT + n0 + tx * 8;
        *(float4*)(crow)     = make_float4(v[0], v[1], v[2], v[3]);
        *(float4*)(crow + 4) = make_float4(v[4], v[5], v[6], v[7]);
    }
}

// ---------------- aggregation (fp16 in, fp32 out) + output head ----------------
__global__ void agg_kernel(const __half* __restrict__ e, float* __restrict__ v)
{
    const int bn = blockIdx.x;
    const int b = bn / N_, n = bn - b * N_;
    const int c = threadIdx.x;
    const __half* base = e + ((size_t)b * E_ + (size_t)n * (N_ - 1)) * H_ + c;
    float s = 0.f;
#pragma unroll 9
    for (int k = 0; k < N_ - 1; ++k) s += __half2float(base[(size_t)k * H_]);
    v[(size_t)bn * H_ + c] = s * (1.0f / N_);
}

__global__ __launch_bounds__(128)
void out_kernel(const __half* __restrict__ e2, const float* __restrict__ wo,
                const float* __restrict__ bo, float* __restrict__ out)
{
    __shared__ float sE[32][260];
    __shared__ float sW[H_ * 4];
    const int tid = threadIdx.x;
    const size_t row0 = (size_t)blockIdx.x * 32;
    for (int i = tid; i < H_ * 4; i += 128) sW[i] = wo[i];
    for (int i = tid; i < 32 * 32; i += 128) {
        const int r = i >> 5, c8 = (i & 31) << 3;
        const __half2* src = (const __half2*)(e2 + (row0 + r) * H_ + c8);
#pragma unroll
        for (int j = 0; j < 4; ++j) {
            float2 f = __half22float2(src[j]);
            sE[r][c8 + 2 * j]     = f.x;
            sE[r][c8 + 2 * j + 1] = f.y;
        }
    }
    __syncthreads();
    const int r = tid >> 2, j = tid & 3;
    float s = bo[j];
#pragma unroll 8
    for (int k = 0; k < H_; ++k) s = fmaf(sE[r][k], sW[k * 4 + j], s);
    out[(row0 + r) * 4 + j] = s;
}

// ---------------- launch ----------------
extern "C" void kernel_launch(void* const* d_in, const int* in_sizes, int n_in,
                              void* d_out, int out_size)
{
    (void)in_sizes; (void)n_in; (void)out_size;
    const float* x   = (const float*)d_in[0];
    const float* w1a = (const float*)d_in[3];
    const float* b1a = (const float*)d_in[4];
    const float* w1b = (const float*)d_in[5];
    const float* b1b = (const float*)d_in[6];
    const float* w2a = (const float*)d_in[7];
    const float* b2a = (const float*)d_in[8];
    const float* w2b = (const float*)d_in[9];
    const float* b2b = (const float*)d_in[10];
    const float* w3a = (const float*)d_in[11];
    const float* b3a = (const float*)d_in[12];
    const float* w3b = (const float*)d_in[13];
    const float* b3b = (const float*)d_in[14];
    const float* w4a = (const float*)d_in[15];
    const float* b4a = (const float*)d_in[16];
    const float* w4b = (const float*)d_in[17];
    const float* b4b = (const float*)d_in[18];
    const float* wo  = (const float*)d_in[19];
    const float* bo  = (const float*)d_in[20];
    float* out = (float*)d_out;

    float *ehidf, *xskipf, *nodeA, *nodeB; __half* wth;
    cudaGetSymbolAddress((void**)&ehidf,  g_ehid);
    cudaGetSymbolAddress((void**)&xskipf, g_xskip);
    cudaGetSymbolAddress((void**)&nodeA, g_nodeA);
    cudaGetSymbolAddress((void**)&nodeB, g_nodeB);
    cudaGetSymbolAddress((void**)&wth,   g_wth);
    __half* xskip16 = (__half*)xskipf;
    __half* e2_16   = (__half*)ehidf;

    __half* f2a = wth;               // K=512
    __half* f2b = wth + 512 * 256;   // K=256
    __half* f4a = wth + 768 * 256;   // K=768
    __half* f4b = wth + 1536 * 256;  // K=256

    cudaFuncSetAttribute(fused_mlp<MODE_E2, 512>, cudaFuncAttributeMaxDynamicSharedMemorySize, SMEM_FUSED_BYTES);
    cudaFuncSetAttribute(fused_mlp<MODE_E3, 768>, cudaFuncAttributeMaxDynamicSharedMemorySize, SMEM_FUSED_BYTES);

    // convert+scatter weights into fp16 frag-ordered layout
    wsplit_k<<<512, 256>>>(w2a, f2a, 512);
    wsplit_k<<<256, 256>>>(w2b, f2b, 256);
    wsplit_k<<<768, 256>>>(w4a, f4a, 768);
    wsplit_k<<<256, 256>>>(w4b, f4b, 256);

    const dim3 blk(256);
    const dim3 gNode(25, 2);

    // MLP1 on nodes (SIMT fp32, exact): x -> nodeA(relu) -> nodeB (=h)
    gemm_k<MODE_X,  NIN_, H_, true ><<<gNode, blk>>>(x,     w1a, b1a, nodeA);
    gemm_k<MODE_DIR, H_,  H_, false><<<gNode, blk>>>(nodeA, w1b, b1b, nodeB);

    // Fused MLP2 on edges: concat(h[recv],h[send]) -> hidden(smem) -> x_skip (fp16)
    fused_mlp<MODE_E2, 512><<<2475, blk, SMEM_FUSED_BYTES>>>(nodeB, nullptr, f2a, b2a, f2b, b2b, xskip16);

    // Aggregate edges->nodes (fp16 -> fp32)
    agg_kernel<<<B_ * N_, 256>>>(xskip16, nodeA);

    // MLP3 on nodes (SIMT fp32): nodeA -> nodeB(relu) -> nodeA (=v)
    gemm_k<MODE_DIR, H_, H_, true ><<<gNode, blk>>>(nodeA, w3a, b3a, nodeB);
    gemm_k<MODE_DIR, H_, H_, false><<<gNode, blk>>>(nodeB, w3b, b3b, nodeA);

    // Fused MLP4 on edges: concat(v[recv],v[send],x_skip) -> hidden(smem) -> e2 (fp16)
    fused_mlp<MODE_E3, 768><<<2475, blk, SMEM_FUSED_BYTES>>>(nodeA, xskip16, f4a, b4a, f4b, b4b, e2_16);

    // Output head
    out_kernel<<<BE_ / 32, 128>>>(e2_16, wo, bo, out);
}

// round 8
// speedup vs baseline: 6.6358x; 1.3967x over previous
#include <cuda_runtime.h>
#include <cuda_fp16.h>
#include <cstdint>

// Problem dims
#define B_   32
#define T_   50
#define N_   100
#define D_   4
#define E_   9900          // N*(N-1)
#define BE_  316800        // B*E
#define H_   256           // hidden
#define NIN_ 200           // T*D

// Scratch (device globals; no allocation allowed)
__device__ float  g_ehid [BE_ * H_];       // used as __half e2 buffer
__device__ float  g_xskip[BE_ * H_];       // used as __half x_skip buffer
__device__ float  g_nodeA[B_ * N_ * H_];   // 3.3 MB
__device__ float  g_nodeB[B_ * N_ * H_];   // 3.3 MB
__device__ float  g_pq   [B_ * N_ * 512];  // P|Q node projections, 6.6 MB
__device__ __half g_wth  [768 * 256];      // frag-ordered fp16 weights: w2b|w4c|w4b

enum { MODE_DIR = 0, MODE_X = 1 };

typedef unsigned long long u64;

// ---------------- small PTX helpers ----------------
__device__ __forceinline__ uint32_t smem_to_u32(const void* p) {
    uint32_t a;
    asm("{ .reg .u64 t; cvta.to.shared.u64 t, %1; cvt.u32.u64 %0, t; }" : "=r"(a) : "l"(p));
    return a;
}
__device__ __forceinline__ uint32_t pkh2(float x, float y) {
    __half2 h = __floats2half2_rn(x, y);
    return *(uint32_t*)&h;
}
__device__ __forceinline__ void cp16(uint32_t s, const void* g) {
    asm volatile("cp.async.cg.shared.global [%0], [%1], 16;" :: "r"(s), "l"(g) : "memory");
}
__device__ __forceinline__ void cp_commit() { asm volatile("cp.async.commit_group;" ::: "memory"); }
__device__ __forceinline__ void cp_wait0()  { asm volatile("cp.async.wait_group 0;" ::: "memory"); }

__device__ __forceinline__ void mma_f16(float* c, const uint32_t* a, uint32_t b0, uint32_t b1) {
    asm volatile(
        "mma.sync.aligned.m16n8k16.row.col.f32.f16.f16.f32 "
        "{%0,%1,%2,%3}, {%4,%5,%6,%7}, {%8,%9}, {%0,%1,%2,%3};"
        : "+f"(c[0]), "+f"(c[1]), "+f"(c[2]), "+f"(c[3])
        : "r"(a[0]), "r"(a[1]), "r"(a[2]), "r"(a[3]), "r"(b0), "r"(b1));
}

// edge index helpers
__device__ __forceinline__ void edge_nodes(int m, int& bn_rcv, int& bn_snd) {
    int b = m / E_, e = m - b * E_;
    int rcv = e / (N_ - 1), jj = e - rcv * (N_ - 1);
    int snd = jj + (jj >= rcv ? 1 : 0);
    bn_rcv = b * N_ + rcv;
    bn_snd = b * N_ + snd;
}

// ==================== fused2: x_skip = relu(P[recv]+Q[send]) @ W2 + b2 ====================
// Block: 128 edge rows, full 256 N. 256 threads = 8 warps (4m x 2n), warp tile 32x128.
// smem: hidden 128 x 132 b32 (67584 B) at 0; B[2] 16 KB each. total 100352 B.
#define F2_SMB(p) (67584u + (p) * 16384u)
#define F2_BYTES  100352

__global__ __launch_bounds__(256, 1)
void fused2(const float* __restrict__ PQ, const __half* __restrict__ W2,
            const float* __restrict__ b2v, __half* __restrict__ C)
{
    extern __shared__ char smem[];
    const uint32_t sbase = smem_to_u32(smem);
    const int tid = threadIdx.x;
    const int m0 = blockIdx.x * 128;

    auto stageB = [&](int t, int p) {
        const char* hs = (const char*)(W2 + (size_t)t * 8192);
        const uint32_t dh = sbase + F2_SMB(p);
#pragma unroll
        for (int i = 0; i < 4; ++i) {
            const int e4 = i * 256 + tid;
            cp16(dh + e4 * 16, hs + e4 * 16);
        }
    };

    stageB(0, 0);
    cp_commit();

    // ---- gather-add: hidden = relu(P[recv] + Q[send]) (bias pre-folded into P) ----
    {
        const int arow = tid >> 1, side = tid & 1;
        int bnr, bns; edge_nodes(m0 + arow, bnr, bns);
        const float4* Pr = (const float4*)(PQ + (size_t)bnr * 512 + side * 128);
        const float4* Qr = (const float4*)(PQ + (size_t)bns * 512 + 256 + side * 128);
        uint32_t* dst = (uint32_t*)smem + arow * 132 + side * 64;
#pragma unroll 8
        for (int j = 0; j < 32; ++j) {
            const float4 p = Pr[j], q = Qr[j];
            const float v0 = fmaxf(p.x + q.x, 0.f), v1 = fmaxf(p.y + q.y, 0.f);
            const float v2 = fmaxf(p.z + q.z, 0.f), v3 = fmaxf(p.w + q.w, 0.f);
            dst[2 * j]     = pkh2(v0, v1);
            dst[2 * j + 1] = pkh2(v2, v3);
        }
    }
    cp_wait0();
    __syncthreads();

    // ---- GEMM2: hidden[128,256] @ W2 ----
    const int wid = tid >> 5, lane = tid & 31;
    const int warp_m = wid >> 1, warp_n = wid & 1;
    const int g = lane >> 2, t4 = lane & 3;

    float acc[2][16][4];
#pragma unroll
    for (int i = 0; i < 2; i++)
#pragma unroll
        for (int j = 0; j < 16; j++)
#pragma unroll
            for (int c = 0; c < 4; c++) acc[i][j][c] = 0.f;

#pragma unroll 1
    for (int t2 = 0; t2 < 8; ++t2) {
        const int p = t2 & 1;
        if (t2 + 1 < 8) { stageB(t2 + 1, p ^ 1); cp_commit(); }
        {
            const uint32_t* sH = (const uint32_t*)smem;
            const uint2*    sB = (const uint2*)(smem + F2_SMB(p));
#pragma unroll
            for (int kk = 0; kk < 2; ++kk) {
                uint32_t a[2][4];
#pragma unroll
                for (int mt = 0; mt < 2; ++mt) {
                    const int r0 = warp_m * 32 + mt * 16 + g;
                    const int cb = t2 * 16 + kk * 8 + t4;
                    a[mt][0] = sH[r0 * 132 + cb];
                    a[mt][1] = sH[(r0 + 8) * 132 + cb];
                    a[mt][2] = sH[r0 * 132 + cb + 4];
                    a[mt][3] = sH[(r0 + 8) * 132 + cb + 4];
                }
#pragma unroll
                for (int nt = 0; nt < 16; ++nt) {
                    const int bi = warp_n * 1024 + ((nt * 2 + kk) * 32 + lane);
                    uint2 b = sB[bi];
#pragma unroll
                    for (int mt = 0; mt < 2; ++mt)
                        mma_f16(acc[mt][nt], a[mt], b.x, b.y);
                }
            }
        }
        cp_wait0();
        __syncthreads();
    }

    // epilogue: bias, fp16 store
#pragma unroll
    for (int mt = 0; mt < 2; ++mt) {
#pragma unroll
        for (int nt = 0; nt < 16; ++nt) {
            const int row = m0 + warp_m * 32 + mt * 16 + g;
            const int col = warp_n * 128 + nt * 8 + t4 * 2;
            const float2 bb = *(const float2*)(b2v + col);
            *(uint32_t*)(C + (size_t)row * 256 + col) =
                pkh2(acc[mt][nt][0] + bb.x, acc[mt][nt][1] + bb.y);
            *(uint32_t*)(C + (size_t)(row + 8) * 256 + col) =
                pkh2(acc[mt][nt][2] + bb.x, acc[mt][nt][3] + bb.y);
        }
    }
}

// ==================== fused4: e2 = (relu(xs@W1 + P4[recv]+Q4[send])) @ W2 + b2 ====================
// smem: A[2] 10240 B; hidden 67584 B @ 20480; B[2] 16 KB each @ 88064. total 120832 B.
#define F4_SMA(p) ((p) * 10240u)
#define F4_SMH    (20480u)
#define F4_SMB(p) (88064u + (p) * 16384u)
#define F4_BYTES  120832

__global__ __launch_bounds__(256, 1)
void fused4(const __half* __restrict__ XS, const float* __restrict__ PQ,
            const __half* __restrict__ W1, const __half* __restrict__ W2,
            const float* __restrict__ b2v, __half* __restrict__ C)
{
    extern __shared__ char smem[];
    const uint32_t sbase = smem_to_u32(smem);
    const int tid = threadIdx.x;
    const int m0 = blockIdx.x * 128;

    const int arow = tid >> 1;
    const int kh   = (tid & 1) << 4;   // half-offset in halves
    const __half* xrow = XS + (size_t)(m0 + arow) * 256;

    auto stageA = [&](int t, int p) {
        const uint32_t dst = sbase + F4_SMA(p) + (arow * 20 + (tid & 1) * 8) * 4;
        const char* src = (const char*)(xrow + t * 32 + kh);
        cp16(dst, src);
        cp16(dst + 16, src + 16);
    };
    auto stageB = [&](const __half* W, int t, int p) {
        const char* hs = (const char*)(W + (size_t)t * 8192);
        const uint32_t dh = sbase + F4_SMB(p);
#pragma unroll
        for (int i = 0; i < 4; ++i) {
            const int e4 = i * 256 + tid;
            cp16(dh + e4 * 16, hs + e4 * 16);
        }
    };

    const int wid = tid >> 5, lane = tid & 31;
    const int warp_m = wid >> 1, warp_n = wid & 1;
    const int g = lane >> 2, t4 = lane & 3;

    float acc[2][16][4];
#pragma unroll
    for (int i = 0; i < 2; i++)
#pragma unroll
        for (int j = 0; j < 16; j++)
#pragma unroll
            for (int c = 0; c < 4; c++) acc[i][j][c] = 0.f;

    // ---- GEMM1: xs[128,256] @ W1 ----
    stageA(0, 0); stageB(W1, 0, 0);
    cp_commit();
    cp_wait0();
    __syncthreads();

#pragma unroll 1
    for (int t = 0; t < 8; ++t) {
        const int p = t & 1;
        if (t + 1 < 8) { stageA(t + 1, p ^ 1); stageB(W1, t + 1, p ^ 1); cp_commit(); }
        {
            const uint32_t* sA = (const uint32_t*)(smem + F4_SMA(p));
            const uint2*    sB = (const uint2*)(smem + F4_SMB(p));
#pragma unroll
            for (int kk = 0; kk < 2; ++kk) {
                uint32_t a[2][4];
#pragma unroll
                for (int mt = 0; mt < 2; ++mt) {
                    const int base = ((warp_m * 2 + mt) * 16 + g) * 20 + kk * 8 + t4;
                    a[mt][0] = sA[base];
                    a[mt][1] = sA[base + 8 * 20];
                    a[mt][2] = sA[base + 4];
                    a[mt][3] = sA[base + 8 * 20 + 4];
                }
#pragma unroll
                for (int nt = 0; nt < 16; ++nt) {
                    const int bi = warp_n * 1024 + ((nt * 2 + kk) * 32 + lane);
                    uint2 b = sB[bi];
#pragma unroll
                    for (int mt = 0; mt < 2; ++mt)
                        mma_f16(acc[mt][nt], a[mt], b.x, b.y);
                }
            }
        }
        cp_wait0();
        __syncthreads();
    }

    // prefetch GEMM2 B tile 0 while doing epilogue 1
    stageB(W2, 0, 0);
    cp_commit();

    // ---- epilogue 1: hidden = relu(acc + P4[recv] + Q4[send]) (b4a folded into P4) ----
    {
        uint32_t* sH = (uint32_t*)(smem + F4_SMH);
#pragma unroll
        for (int mt = 0; mt < 2; ++mt) {
#pragma unroll
            for (int rr = 0; rr < 2; ++rr) {
                const int rloc = warp_m * 32 + mt * 16 + g + rr * 8;
                int bnr, bns; edge_nodes(m0 + rloc, bnr, bns);
                const float* Pr = PQ + (size_t)bnr * 512;
                const float* Qr = PQ + (size_t)bns * 512 + 256;
#pragma unroll
                for (int nt = 0; nt < 16; ++nt) {
                    const int col = warp_n * 128 + nt * 8 + t4 * 2;
                    const float2 p = *(const float2*)(Pr + col);
                    const float2 q = *(const float2*)(Qr + col);
                    const float v0 = fmaxf(acc[mt][nt][rr * 2 + 0] + p.x + q.x, 0.f);
                    const float v1 = fmaxf(acc[mt][nt][rr * 2 + 1] + p.y + q.y, 0.f);
                    sH[rloc * 132 + warp_n * 64 + nt * 4 + t4] = pkh2(v0, v1);
                }
            }
        }
    }
#pragma unroll
    for (int i = 0; i < 2; i++)
#pragma unroll
        for (int j = 0; j < 16; j++)
#pragma unroll
            for (int c = 0; c < 4; c++) acc[i][j][c] = 0.f;

    cp_wait0();
    __syncthreads();

    // ---- GEMM2: hidden @ W2 ----
#pragma unroll 1
    for (int t2 = 0; t2 < 8; ++t2) {
        const int p = t2 & 1;
        if (t2 + 1 < 8) { stageB(W2, t2 + 1, p ^ 1); cp_commit(); }
        {
            const uint32_t* sH = (const uint32_t*)(smem + F4_SMH);
            const uint2*    sB = (const uint2*)(smem + F4_SMB(p));
#pragma unroll
            for (int kk = 0; kk < 2; ++kk) {
                uint32_t a[2][4];
#pragma unroll
                for (int mt = 0; mt < 2; ++mt) {
                    const int r0 = warp_m * 32 + mt * 16 + g;
                    const int cb = t2 * 16 + kk * 8 + t4;
                    a[mt][0] = sH[r0 * 132 + cb];
                    a[mt][1] = sH[(r0 + 8) * 132 + cb];
                    a[mt][2] = sH[r0 * 132 + cb + 4];
                    a[mt][3] = sH[(r0 + 8) * 132 + cb + 4];
                }
#pragma unroll
                for (int nt = 0; nt < 16; ++nt) {
                    const int bi = warp_n * 1024 + ((nt * 2 + kk) * 32 + lane);
                    uint2 b = sB[bi];
#pragma unroll
                    for (int mt = 0; mt < 2; ++mt)
                        mma_f16(acc[mt][nt], a[mt], b.x, b.y);
                }
            }
        }
        cp_wait0();
        __syncthreads();
    }

    // epilogue 2: bias, fp16 store
#pragma unroll
    for (int mt = 0; mt < 2; ++mt) {
#pragma unroll
        for (int nt = 0; nt < 16; ++nt) {
            const int row = m0 + warp_m * 32 + mt * 16 + g;
            const int col = warp_n * 128 + nt * 8 + t4 * 2;
            const float2 bb = *(const float2*)(b2v + col);
            *(uint32_t*)(C + (size_t)row * 256 + col) =
                pkh2(acc[mt][nt][0] + bb.x, acc[mt][nt][1] + bb.y);
            *(uint32_t*)(C + (size_t)(row + 8) * 256 + col) =
                pkh2(acc[mt][nt][2] + bb.x, acc[mt][nt][3] + bb.y);
        }
    }
}

// ---------------- weight fp16-convert + frag-order scatter (K=256) ----------------
__global__ void wsplit_k(const float* __restrict__ w, __half* __restrict__ oh, int K)
{
    const int idx = blockIdx.x * 256 + threadIdx.x;   // = k*256 + n
    const int k = idx >> 8, n = idx & 255;
    const __half hv = __float2half_rn(w[idx]);
    const int ny = n >> 7, nr = n & 127;
    const int nt = nr >> 3, gg = nr & 7;
    const int s = k >> 5, kr = k & 31;
    const int kk = kr >> 4, kr16 = kr & 15;
    const int reg = (kr16 >= 8) ? 1 : 0;
    const int t4 = (kr16 & 7) >> 1;
    const int hp = kr16 & 1;
    const int lane = gg * 4 + t4;
    const int dst = (s * 2 + ny) * 4096 + ((nt * 2 + kk) * 32 + lane) * 4 + reg * 2 + hp;
    oh[dst] = hv;
}

// ---------------- SIMT f32x2 GEMM (node layers, exact fp32) ----------------
__device__ __forceinline__ u64 pk2(float lo, float hi) {
    u64 r; asm("mov.b64 %0, {%1, %2};" : "=l"(r) : "f"(lo), "f"(hi)); return r;
}
__device__ __forceinline__ void fma2(u64& d, u64 a, u64 b) {
    asm("fma.rn.f32x2 %0, %1, %2, %0;" : "+l"(d) : "l"(a), "l"(b));
}
__device__ __forceinline__ void unpk2(float& lo, float& hi, u64 v) {
    asm("mov.b64 {%0, %1}, %2;" : "=f"(lo), "=f"(hi) : "l"(v));
}

template<int MODE, int K, int NOUT, bool RELU>
__global__ __launch_bounds__(256, 2)
void gemm_k(const float* __restrict__ A, const float* __restrict__ W,
            const float* __restrict__ bias, float* __restrict__ C)
{
    constexpr int TM = 128, TN = 128, TK = 8;
    __shared__ float sA[2][TK][TM + 4];
    __shared__ __align__(16) float sB[2][TK][TN];

    const int tid = threadIdx.x;
    const int m0 = blockIdx.x * TM, n0 = blockIdx.y * TN;
    const int a_m = tid >> 1, a_k = (tid & 1) << 2;
    const int b_k = tid >> 5, b_n = (tid & 31) << 2;

    const int m = m0 + a_m;
    const float* pr;
    if (MODE == MODE_DIR) {
        pr = A + (size_t)m * K;
    } else { // MODE_X
        int b = m / N_, n = m - b * N_;
        pr = A + (size_t)b * (T_ * N_ * D_) + (size_t)n * D_;
    }
    auto ldA = [&](int k0) -> float4 {
        const int k = k0 + a_k;
        if (MODE == MODE_DIR) return *(const float4*)(pr + k);
        return *(const float4*)(pr + (size_t)(k >> 2) * (N_ * D_));
    };
    auto ldB = [&](int k0) -> float4 {
        return *(const float4*)(W + (size_t)(k0 + b_k) * NOUT + n0 + b_n);
    };

    const int tx = tid & 15, ty = tid >> 4;
    u64 acc[8][4];
#pragma unroll
    for (int i = 0; i < 8; i++)
#pragma unroll
        for (int j = 0; j < 4; j++) acc[i][j] = 0ull;

    constexpr int S = K / TK;
    {
        float4 ra = ldA(0), rb = ldB(0);
        sA[0][a_k + 0][a_m] = ra.x; sA[0][a_k + 1][a_m] = ra.y;
        sA[0][a_k + 2][a_m] = ra.z; sA[0][a_k + 3][a_m] = ra.w;
        *(float4*)&sB[0][b_k][b_n] = rb;
    }
    __syncthreads();
    for (int s = 0; s < S; ++s) {
        const int cur = s & 1;
        float4 na, nb;
        if (s + 1 < S) { na = ldA((s + 1) * TK); nb = ldB((s + 1) * TK); }
#pragma unroll
        for (int k = 0; k < TK; ++k) {
            float4 a0 = *(const float4*)&sA[cur][k][ty * 8];
            float4 a1 = *(const float4*)&sA[cur][k][ty * 8 + 4];
            ulonglong2 bq0 = *(const ulonglong2*)&sB[cur][k][tx * 8];
            ulonglong2 bq1 = *(const ulonglong2*)&sB[cur][k][tx * 8 + 4];
            u64 bv[4] = {bq0.x, bq0.y, bq1.x, bq1.y};
            float av[8] = {a0.x, a0.y, a0.z, a0.w, a1.x, a1.y, a1.z, a1.w};
#pragma unroll
            for (int i = 0; i < 8; i++) {
                u64 ap = pk2(av[i], av[i]);
#pragma unroll
                for (int j = 0; j < 4; j++) fma2(acc[i][j], ap, bv[j]);
            }
        }
        if (s + 1 < S) {
            const int nxt = cur ^ 1;
            sA[nxt][a_k + 0][a_m] = na.x; sA[nxt][a_k + 1][a_m] = na.y;
            sA[nxt][a_k + 2][a_m] = na.z; sA[nxt][a_k + 3][a_m] = na.w;
            *(float4*)&sB[nxt][b_k][b_n] = nb;
        }
        __syncthreads();
    }
    float bb[8];
#pragma unroll
    for (int j = 0; j < 8; j++) bb[j] = bias[n0 + tx * 8 + j];
#pragma unroll
    for (int i = 0; i < 8; i++) {
        float v[8];
#pragma unroll
        for (int j = 0; j < 4; j++) {
            float lo, hi; unpk2(lo, hi, acc[i][j]);
            float t0 = lo + bb[2 * j], t1 = hi + bb[2 * j + 1];
            v[2 * j]     = RELU ? fmaxf(t0, 0.f) : t0;
            v[2 * j + 1] = RELU ? fmaxf(t1, 0.f) : t1;
        }
        float* crow = C + (size_t)(m0 + ty * 8 + i) * NOUT + n0 + tx * 8;
        *(float4*)(crow)     = make_float4(v[0], v[1], v[2], v[3]);
        *(float4*)(crow + 4) = make_float4(v[4], v[5], v[6], v[7]);
    }
}

// ---------------- gemm_pq: PQ[M,512] = A[M,256] @ {W_top|W_bot}[256,256] ----------------
// grid (M/128, 4): y&1 = n-half, y>>1 = P(0)/Q(1). Bias added only to P half.
__global__ __launch_bounds__(256, 2)
void gemm_pq(const float* __restrict__ A, const float* __restrict__ W,
             const float* __restrict__ bias, float* __restrict__ C)
{
    constexpr int K = 256, TK = 8;
    __shared__ float sA[2][TK][132];
    __shared__ __align__(16) float sB[2][TK][128];

    const int tid = threadIdx.x;
    const int m0 = blockIdx.x * 128;
    const int half = blockIdx.y >> 1;
    const int n0 = (blockIdx.y & 1) * 128;
    const float* Wb = W + (size_t)half * 256 * 256;

    const int a_m = tid >> 1, a_k = (tid & 1) << 2;
    const int b_k = tid >> 5, b_n = (tid & 31) << 2;
    const float* pr = A + (size_t)(m0 + a_m) * K;

    auto ldB = [&](int k0) -> float4 {
        return *(const float4*)(Wb + (size_t)(k0 + b_k) * 256 + n0 + b_n);
    };

    const int tx = tid & 15, ty = tid >> 4;
    u64 acc[8][4];
#pragma unroll
    for (int i = 0; i < 8; i++)
#pragma unroll
        for (int j = 0; j < 4; j++) acc[i][j] = 0ull;

    {
        float4 ra = *(const float4*)(pr + a_k), rb = ldB(0);
        sA[0][a_k + 0][a_m] = ra.x; sA[0][a_k + 1][a_m] = ra.y;
        sA[0][a_k + 2][a_m] = ra.z; sA[0][a_k + 3][a_m] = ra.w;
        *(float4*)&sB[0][b_k][b_n] = rb;
    }
    __syncthreads();
    for (int s = 0; s < K / TK; ++s) {
        const int cur = s & 1;
        float4 na, nb;
        if (s + 1 < K / TK) { na = *(const float4*)(pr + (s + 1) * TK + a_k); nb = ldB((s + 1) * TK); }
#pragma unroll
        for (int k = 0; k < TK; ++k) {
            float4 a0 = *(const float4*)&sA[cur][k][ty * 8];
            float4 a1 = *(const float4*)&sA[cur][k][ty * 8 + 4];
            ulonglong2 bq0 = *(const ulonglong2*)&sB[cur][k][tx * 8];
            ulonglong2 bq1 = *(const ulonglong2*)&sB[cur][k][tx * 8 + 4];
            u64 bv[4] = {bq0.x, bq0.y, bq1.x, bq1.y};
            float av[8] = {a0.x, a0.y, a0.z, a0.w, a1.x, a1.y, a1.z, a1.w};
#pragma unroll
            for (int i = 0; i < 8; i++) {
                u64 ap = pk2(av[i], av[i]);
#pragma unroll
                for (int j = 0; j < 4; j++) fma2(acc[i][j], ap, bv[j]);
            }
        }
        if (s + 1 < K / TK) {
            const int nxt = cur ^ 1;
            sA[nxt][a_k + 0][a_m] = na.x; sA[nxt][a_k + 1][a_m] = na.y;
            sA[nxt][a_k + 2][a_m] = na.z; sA[nxt][a_k + 3][a_m] = na.w;
            *(float4*)&sB[nxt][b_k][b_n] = nb;
        }
        __syncthreads();
    }
    float bb[8];
#pragma unroll
    for (int j = 0; j < 8; j++) bb[j] = half ? 0.f : bias[n0 + tx * 8 + j];
#pragma unroll
    for (int i = 0; i < 8; i++) {
        float v[8];
#pragma unroll
        for (int j = 0; j < 4; j++) {
            float lo, hi; unpk2(lo, hi, acc[i][j]);
            v[2 * j]     = lo + bb[2 * j];
            v[2 * j + 1] = hi + bb[2 * j + 1];
        }
        float* crow = C + (size_t)(m0 + ty * 8 + i) * 512 + half * 256 + n0 + tx * 8;
        *(float4*)(crow)     = make_float4(v[0], v[1], v[2], v[3]);
        *(float4*)(crow + 4) = make_float4(v[4], v[5], v[6], v[7]);
    }
}

// ---------------- aggregation (fp16 in, fp32 out) + output head ----------------
__global__ void agg_kernel(const __half* __restrict__ e, float* __restrict__ v)
{
    const int bn = blockIdx.x;
    const int b = bn / N_, n = bn - b * N_;
    const int c = threadIdx.x;
    const __half* base = e + ((size_t)b * E_ + (size_t)n * (N_ - 1)) * H_ + c;
    float s = 0.f;
#pragma unroll 9
    for (int k = 0; k < N_ - 1; ++k) s += __half2float(base[(size_t)k * H_]);
    v[(size_t)bn * H_ + c] = s * (1.0f / N_);
}

__global__ __launch_bounds__(128)
void out_kernel(const __half* __restrict__ e2, const float* __restrict__ wo,
                const float* __restrict__ bo, float* __restrict__ out)
{
    __shared__ float sE[32][260];
    __shared__ float sW[H_ * 4];
    const int tid = threadIdx.x;
    const size_t row0 = (size_t)blockIdx.x * 32;
    for (int i = tid; i < H_ * 4; i += 128) sW[i] = wo[i];
    for (int i = tid; i < 32 * 32; i += 128) {
        const int r = i >> 5, c8 = (i & 31) << 3;
        const __half2* src = (const __half2*)(e2 + (row0 + r) * H_ + c8);
#pragma unroll
        for (int j = 0; j < 4; ++j) {
            float2 f = __half22float2(src[j]);
            sE[r][c8 + 2 * j]     = f.x;
            sE[r][c8 + 2 * j + 1] = f.y;
        }
    }
    __syncthreads();
    const int r = tid >> 2, j = tid & 3;
    float s = bo[j];
#pragma unroll 8
    for (int k = 0; k < H_; ++k) s = fmaf(sE[r][k], sW[k * 4 + j], s);
    out[(row0 + r) * 4 + j] = s;
}

// ---------------- launch ----------------
extern "C" void kernel_launch(void* const* d_in, const int* in_sizes, int n_in,
                              void* d_out, int out_size)
{
    (void)in_sizes; (void)n_in; (void)out_size;
    const float* x   = (const float*)d_in[0];
    const float* w1a = (const float*)d_in[3];
    const float* b1a = (const float*)d_in[4];
    const float* w1b = (const float*)d_in[5];
    const float* b1b = (const float*)d_in[6];
    const float* w2a = (const float*)d_in[7];
    const float* b2a = (const float*)d_in[8];
    const float* w2b = (const float*)d_in[9];
    const float* b2b = (const float*)d_in[10];
    const float* w3a = (const float*)d_in[11];
    const float* b3a = (const float*)d_in[12];
    const float* w3b = (const float*)d_in[13];
    const float* b3b = (const float*)d_in[14];
    const float* w4a = (const float*)d_in[15];
    const float* b4a = (const float*)d_in[16];
    const float* w4b = (const float*)d_in[17];
    const float* b4b = (const float*)d_in[18];
    const float* wo  = (const float*)d_in[19];
    const float* bo  = (const float*)d_in[20];
    float* out = (float*)d_out;

    float *ehidf, *xskipf, *nodeA, *nodeB, *pq; __half* wth;
    cudaGetSymbolAddress((void**)&ehidf,  g_ehid);
    cudaGetSymbolAddress((void**)&xskipf, g_xskip);
    cudaGetSymbolAddress((void**)&nodeA, g_nodeA);
    cudaGetSymbolAddress((void**)&nodeB, g_nodeB);
    cudaGetSymbolAddress((void**)&pq,    g_pq);
    cudaGetSymbolAddress((void**)&wth,   g_wth);
    __half* xskip16 = (__half*)xskipf;
    __half* e2_16   = (__half*)ehidf;

    __half* f2b = wth;               // w2b, K=256
    __half* f4c = wth + 256 * 256;   // w4a[512:768], K=256 (x_skip block)
    __half* f4b = wth + 512 * 256;   // w4b, K=256

    cudaFuncSetAttribute(fused2, cudaFuncAttributeMaxDynamicSharedMemorySize, F2_BYTES);
    cudaFuncSetAttribute(fused4, cudaFuncAttributeMaxDynamicSharedMemorySize, F4_BYTES);

    // convert+scatter weights into fp16 frag-ordered layout
    wsplit_k<<<256, 256>>>(w2b, f2b, 256);
    wsplit_k<<<256, 256>>>(w4a + 512 * 256, f4c, 256);
    wsplit_k<<<256, 256>>>(w4b, f4b, 256);

    const dim3 blk(256);
    const dim3 gNode(25, 2);
    const dim3 gPQ(25, 4);

    // MLP1 on nodes (SIMT fp32, exact): x -> nodeA(relu) -> nodeB (=h)
    gemm_k<MODE_X,  NIN_, H_, true ><<<gNode, blk>>>(x,     w1a, b1a, nodeA);
    gemm_k<MODE_DIR, H_,  H_, false><<<gNode, blk>>>(nodeA, w1b, b1b, nodeB);

    // Node projections for MLP2: PQ = [h@w2a_top + b2a | h@w2a_bot]
    gemm_pq<<<gPQ, blk>>>(nodeB, w2a, b2a, pq);

    // Fused MLP2 on edges: relu(P[recv]+Q[send]) @ w2b + b2b -> x_skip (fp16)
    fused2<<<2475, blk, F2_BYTES>>>(pq, f2b, b2b, xskip16);

    // Aggregate edges->nodes (fp16 -> fp32)
    agg_kernel<<<B_ * N_, 256>>>(xskip16, nodeA);

    // MLP3 on nodes (SIMT fp32): nodeA -> nodeB(relu) -> nodeA (=v)
    gemm_k<MODE_DIR, H_, H_, true ><<<gNode, blk>>>(nodeA, w3a, b3a, nodeB);
    gemm_k<MODE_DIR, H_, H_, false><<<gNode, blk>>>(nodeB, w3b, b3b, nodeA);

    // Node projections for MLP4: PQ = [v@w4a_top + b4a | v@w4a_mid]
    gemm_pq<<<gPQ, blk>>>(nodeA, w4a, b4a, pq);

    // Fused MLP4 on edges: relu(xs@w4a_xs + P4[recv]+Q4[send]) @ w4b + b4b -> e2 (fp16)
    fused4<<<2475, blk, F4_BYTES>>>(xskip16, pq, f4c, f4b, b4b, e2_16);

    // Output head
    out_kernel<<<BE_ / 32, 128>>>(e2_16, wo, bo, out);
}

// round 9
// speedup vs baseline: 8.1357x; 1.2260x over previous
#include <cuda_runtime.h>
#include <cuda_fp16.h>
#include <cstdint>

// Problem dims
#define B_   32
#define T_   50
#define N_   100
#define D_   4
#define E_   9900          // N*(N-1)
#define BE_  316800        // B*E
#define H_   256           // hidden
#define NIN_ 200           // T*D

// Scratch (device globals; no allocation allowed)
__device__ float  g_xskip[BE_ * H_ / 2];   // __half x_skip buffer (162 MB)
__device__ float  g_nodeA[B_ * N_ * H_];   // 3.3 MB
__device__ float  g_nodeB[B_ * N_ * H_];   // 3.3 MB
__device__ float  g_pq   [B_ * N_ * 512];  // P|Q node projections, 6.6 MB
__device__ __half g_wth  [768 * 256];      // frag-ordered fp16 weights: w2b|w4c|w4b

enum { MODE_DIR = 0, MODE_X = 1 };

typedef unsigned long long u64;

// ---------------- small PTX helpers ----------------
__device__ __forceinline__ uint32_t smem_to_u32(const void* p) {
    uint32_t a;
    asm("{ .reg .u64 t; cvta.to.shared.u64 t, %1; cvt.u32.u64 %0, t; }" : "=r"(a) : "l"(p));
    return a;
}
__device__ __forceinline__ uint32_t pkh2(float x, float y) {
    __half2 h = __floats2half2_rn(x, y);
    return *(uint32_t*)&h;
}
__device__ __forceinline__ void cp16(uint32_t s, const void* g) {
    asm volatile("cp.async.cg.shared.global [%0], [%1], 16;" :: "r"(s), "l"(g) : "memory");
}
__device__ __forceinline__ void cp_commit() { asm volatile("cp.async.commit_group;" ::: "memory"); }
__device__ __forceinline__ void cp_wait0()  { asm volatile("cp.async.wait_group 0;" ::: "memory"); }

__device__ __forceinline__ void mma_f16(float* c, const uint32_t* a, uint32_t b0, uint32_t b1) {
    asm volatile(
        "mma.sync.aligned.m16n8k16.row.col.f32.f16.f16.f32 "
        "{%0,%1,%2,%3}, {%4,%5,%6,%7}, {%8,%9}, {%0,%1,%2,%3};"
        : "+f"(c[0]), "+f"(c[1]), "+f"(c[2]), "+f"(c[3])
        : "r"(a[0]), "r"(a[1]), "r"(a[2]), "r"(a[3]), "r"(b0), "r"(b1));
}

// edge index helpers
__device__ __forceinline__ void edge_nodes(int m, int& bn_rcv, int& bn_snd) {
    int b = m / E_, e = m - b * E_;
    int rcv = e / (N_ - 1), jj = e - rcv * (N_ - 1);
    int snd = jj + (jj >= rcv ? 1 : 0);
    bn_rcv = b * N_ + rcv;
    bn_snd = b * N_ + snd;
}

// SIMT f32x2 primitives
__device__ __forceinline__ u64 pk2(float lo, float hi) {
    u64 r; asm("mov.b64 %0, {%1, %2};" : "=l"(r) : "f"(lo), "f"(hi)); return r;
}
__device__ __forceinline__ void fma2(u64& d, u64 a, u64 b) {
    asm("fma.rn.f32x2 %0, %1, %2, %0;" : "+l"(d) : "l"(a), "l"(b));
}
__device__ __forceinline__ void unpk2(float& lo, float& hi, u64 v) {
    asm("mov.b64 {%0, %1}, %2;" : "=f"(lo), "=f"(hi) : "l"(v));
}

// ==================== fused2: x_skip = relu(P[recv]+Q[send]) @ W2 + b2 ====================
#define F2_SMB(p) (67584u + (p) * 16384u)
#define F2_BYTES  100352

__global__ __launch_bounds__(256, 1)
void fused2(const float* __restrict__ PQ, const __half* __restrict__ W2,
            const float* __restrict__ b2v, __half* __restrict__ C)
{
    extern __shared__ char smem[];
    const uint32_t sbase = smem_to_u32(smem);
    const int tid = threadIdx.x;
    const int m0 = blockIdx.x * 128;

    auto stageB = [&](int t, int p) {
        const char* hs = (const char*)(W2 + (size_t)t * 8192);
        const uint32_t dh = sbase + F2_SMB(p);
#pragma unroll
        for (int i = 0; i < 4; ++i) {
            const int e4 = i * 256 + tid;
            cp16(dh + e4 * 16, hs + e4 * 16);
        }
    };

    stageB(0, 0);
    cp_commit();

    // ---- gather-add: hidden = relu(P[recv] + Q[send]) (bias pre-folded into P) ----
    {
        const int arow = tid >> 1, side = tid & 1;
        int bnr, bns; edge_nodes(m0 + arow, bnr, bns);
        const float4* Pr = (const float4*)(PQ + (size_t)bnr * 512 + side * 128);
        const float4* Qr = (const float4*)(PQ + (size_t)bns * 512 + 256 + side * 128);
        uint32_t* dst = (uint32_t*)smem + arow * 132 + side * 64;
#pragma unroll 8
        for (int j = 0; j < 32; ++j) {
            const float4 p = Pr[j], q = Qr[j];
            const float v0 = fmaxf(p.x + q.x, 0.f), v1 = fmaxf(p.y + q.y, 0.f);
            const float v2 = fmaxf(p.z + q.z, 0.f), v3 = fmaxf(p.w + q.w, 0.f);
            dst[2 * j]     = pkh2(v0, v1);
            dst[2 * j + 1] = pkh2(v2, v3);
        }
    }
    cp_wait0();
    __syncthreads();

    // ---- GEMM2: hidden[128,256] @ W2 ----
    const int wid = tid >> 5, lane = tid & 31;
    const int warp_m = wid >> 1, warp_n = wid & 1;
    const int g = lane >> 2, t4 = lane & 3;

    float acc[2][16][4];
#pragma unroll
    for (int i = 0; i < 2; i++)
#pragma unroll
        for (int j = 0; j < 16; j++)
#pragma unroll
            for (int c = 0; c < 4; c++) acc[i][j][c] = 0.f;

#pragma unroll 1
    for (int t2 = 0; t2 < 8; ++t2) {
        const int p = t2 & 1;
        if (t2 + 1 < 8) { stageB(t2 + 1, p ^ 1); cp_commit(); }
        {
            const uint32_t* sH = (const uint32_t*)smem;
            const uint2*    sB = (const uint2*)(smem + F2_SMB(p));
#pragma unroll
            for (int kk = 0; kk < 2; ++kk) {
                uint32_t a[2][4];
#pragma unroll
                for (int mt = 0; mt < 2; ++mt) {
                    const int r0 = warp_m * 32 + mt * 16 + g;
                    const int cb = t2 * 16 + kk * 8 + t4;
                    a[mt][0] = sH[r0 * 132 + cb];
                    a[mt][1] = sH[(r0 + 8) * 132 + cb];
                    a[mt][2] = sH[r0 * 132 + cb + 4];
                    a[mt][3] = sH[(r0 + 8) * 132 + cb + 4];
                }
#pragma unroll
                for (int nt = 0; nt < 16; ++nt) {
                    const int bi = warp_n * 1024 + ((nt * 2 + kk) * 32 + lane);
                    uint2 b = sB[bi];
#pragma unroll
                    for (int mt = 0; mt < 2; ++mt)
                        mma_f16(acc[mt][nt], a[mt], b.x, b.y);
                }
            }
        }
        cp_wait0();
        __syncthreads();
    }

    // epilogue: bias, fp16 store
#pragma unroll
    for (int mt = 0; mt < 2; ++mt) {
#pragma unroll
        for (int nt = 0; nt < 16; ++nt) {
            const int row = m0 + warp_m * 32 + mt * 16 + g;
            const int col = warp_n * 128 + nt * 8 + t4 * 2;
            const float2 bb = *(const float2*)(b2v + col);
            *(uint32_t*)(C + (size_t)row * 256 + col) =
                pkh2(acc[mt][nt][0] + bb.x, acc[mt][nt][1] + bb.y);
            *(uint32_t*)(C + (size_t)(row + 8) * 256 + col) =
                pkh2(acc[mt][nt][2] + bb.x, acc[mt][nt][3] + bb.y);
        }
    }
}

// ==================== fused4 + output head ====================
// out[M,4] = (relu(xs@W1 + P4[recv]+Q4[send]) @ W2 + b2) @ wo + bo
#define F4_SMA(p) ((p) * 10240u)
#define F4_SMH    (20480u)
#define F4_SMB(p) (88064u + (p) * 16384u)
#define F4_BYTES  120832

__global__ __launch_bounds__(256, 1)
void fused4(const __half* __restrict__ XS, const float* __restrict__ PQ,
            const __half* __restrict__ W1, const __half* __restrict__ W2,
            const float* __restrict__ b2v, const float* __restrict__ wo,
            const float* __restrict__ bo, float* __restrict__ out)
{
    extern __shared__ char smem[];
    const uint32_t sbase = smem_to_u32(smem);
    const int tid = threadIdx.x;
    const int m0 = blockIdx.x * 128;

    const int arow = tid >> 1;
    const int kh   = (tid & 1) << 4;
    const __half* xrow = XS + (size_t)(m0 + arow) * 256;

    auto stageA = [&](int t, int p) {
        const uint32_t dst = sbase + F4_SMA(p) + (arow * 20 + (tid & 1) * 8) * 4;
        const char* src = (const char*)(xrow + t * 32 + kh);
        cp16(dst, src);
        cp16(dst + 16, src + 16);
    };
    auto stageB = [&](const __half* W, int t, int p) {
        const char* hs = (const char*)(W + (size_t)t * 8192);
        const uint32_t dh = sbase + F4_SMB(p);
#pragma unroll
        for (int i = 0; i < 4; ++i) {
            const int e4 = i * 256 + tid;
            cp16(dh + e4 * 16, hs + e4 * 16);
        }
    };

    const int wid = tid >> 5, lane = tid & 31;
    const int warp_m = wid >> 1, warp_n = wid & 1;
    const int g = lane >> 2, t4 = lane & 3;

    float acc[2][16][4];
#pragma unroll
    for (int i = 0; i < 2; i++)
#pragma unroll
        for (int j = 0; j < 16; j++)
#pragma unroll
            for (int c = 0; c < 4; c++) acc[i][j][c] = 0.f;

    // ---- GEMM1: xs[128,256] @ W1 ----
    stageA(0, 0); stageB(W1, 0, 0);
    cp_commit();
    cp_wait0();
    __syncthreads();

#pragma unroll 1
    for (int t = 0; t < 8; ++t) {
        const int p = t & 1;
        if (t + 1 < 8) { stageA(t + 1, p ^ 1); stageB(W1, t + 1, p ^ 1); cp_commit(); }
        {
            const uint32_t* sA = (const uint32_t*)(smem + F4_SMA(p));
            const uint2*    sB = (const uint2*)(smem + F4_SMB(p));
#pragma unroll
            for (int kk = 0; kk < 2; ++kk) {
                uint32_t a[2][4];
#pragma unroll
                for (int mt = 0; mt < 2; ++mt) {
                    const int base = ((warp_m * 2 + mt) * 16 + g) * 20 + kk * 8 + t4;
                    a[mt][0] = sA[base];
                    a[mt][1] = sA[base + 8 * 20];
                    a[mt][2] = sA[base + 4];
                    a[mt][3] = sA[base + 8 * 20 + 4];
                }
#pragma unroll
                for (int nt = 0; nt < 16; ++nt) {
                    const int bi = warp_n * 1024 + ((nt * 2 + kk) * 32 + lane);
                    uint2 b = sB[bi];
#pragma unroll
                    for (int mt = 0; mt < 2; ++mt)
                        mma_f16(acc[mt][nt], a[mt], b.x, b.y);
                }
            }
        }
        cp_wait0();
        __syncthreads();
    }

    // prefetch GEMM2 B tile 0 while doing epilogue 1
    stageB(W2, 0, 0);
    cp_commit();

    // ---- epilogue 1: hidden = relu(acc + P4[recv] + Q4[send]) (b4a folded into P4) ----
    {
        uint32_t* sH = (uint32_t*)(smem + F4_SMH);
#pragma unroll
        for (int mt = 0; mt < 2; ++mt) {
#pragma unroll
            for (int rr = 0; rr < 2; ++rr) {
                const int rloc = warp_m * 32 + mt * 16 + g + rr * 8;
                int bnr, bns; edge_nodes(m0 + rloc, bnr, bns);
                const float* Pr = PQ + (size_t)bnr * 512;
                const float* Qr = PQ + (size_t)bns * 512 + 256;
#pragma unroll
                for (int nt = 0; nt < 16; ++nt) {
                    const int col = warp_n * 128 + nt * 8 + t4 * 2;
                    const float2 p = *(const float2*)(Pr + col);
                    const float2 q = *(const float2*)(Qr + col);
                    const float v0 = fmaxf(acc[mt][nt][rr * 2 + 0] + p.x + q.x, 0.f);
                    const float v1 = fmaxf(acc[mt][nt][rr * 2 + 1] + p.y + q.y, 0.f);
                    sH[rloc * 132 + warp_n * 64 + nt * 4 + t4] = pkh2(v0, v1);
                }
            }
        }
    }
#pragma unroll
    for (int i = 0; i < 2; i++)
#pragma unroll
        for (int j = 0; j < 16; j++)
#pragma unroll
            for (int c = 0; c < 4; c++) acc[i][j][c] = 0.f;

    cp_wait0();
    __syncthreads();

    // ---- GEMM2: hidden @ W2 ----
#pragma unroll 1
    for (int t2 = 0; t2 < 8; ++t2) {
        const int p = t2 & 1;
        if (t2 + 1 < 8) { stageB(W2, t2 + 1, p ^ 1); cp_commit(); }
        {
            const uint32_t* sH = (const uint32_t*)(smem + F4_SMH);
            const uint2*    sB = (const uint2*)(smem + F4_SMB(p));
#pragma unroll
            for (int kk = 0; kk < 2; ++kk) {
                uint32_t a[2][4];
#pragma unroll
                for (int mt = 0; mt < 2; ++mt) {
                    const int r0 = warp_m * 32 + mt * 16 + g;
                    const int cb = t2 * 16 + kk * 8 + t4;
                    a[mt][0] = sH[r0 * 132 + cb];
                    a[mt][1] = sH[(r0 + 8) * 132 + cb];
                    a[mt][2] = sH[r0 * 132 + cb + 4];
                    a[mt][3] = sH[(r0 + 8) * 132 + cb + 4];
                }
#pragma unroll
                for (int nt = 0; nt < 16; ++nt) {
                    const int bi = warp_n * 1024 + ((nt * 2 + kk) * 32 + lane);
                    uint2 b = sB[bi];
#pragma unroll
                    for (int mt = 0; mt < 2; ++mt)
                        mma_f16(acc[mt][nt], a[mt], b.x, b.y);
                }
            }
        }
        cp_wait0();
        __syncthreads();
    }

    // ---- epilogue 2: output head. out = (acc + b4b) @ wo + bo ----
    {
        float p[2][2][4];
#pragma unroll
        for (int mt = 0; mt < 2; ++mt)
#pragma unroll
            for (int rr = 0; rr < 2; ++rr)
#pragma unroll
                for (int j = 0; j < 4; ++j) p[mt][rr][j] = 0.f;

#pragma unroll
        for (int nt = 0; nt < 16; ++nt) {
            const int col = warp_n * 128 + nt * 8 + t4 * 2;
            const float2 bb = *(const float2*)(b2v + col);
            const float4 w0 = *(const float4*)(wo + col * 4);
            const float4 w1 = *(const float4*)(wo + (col + 1) * 4);
#pragma unroll
            for (int mt = 0; mt < 2; ++mt)
#pragma unroll
                for (int rr = 0; rr < 2; ++rr) {
                    const float v0 = acc[mt][nt][rr * 2 + 0] + bb.x;
                    const float v1 = acc[mt][nt][rr * 2 + 1] + bb.y;
                    p[mt][rr][0] += v0 * w0.x + v1 * w1.x;
                    p[mt][rr][1] += v0 * w0.y + v1 * w1.y;
                    p[mt][rr][2] += v0 * w0.z + v1 * w1.z;
                    p[mt][rr][3] += v0 * w0.w + v1 * w1.w;
                }
        }
        // reduce over t4 lanes (lane = g*4 + t4)
#pragma unroll
        for (int mt = 0; mt < 2; ++mt)
#pragma unroll
            for (int rr = 0; rr < 2; ++rr)
#pragma unroll
                for (int j = 0; j < 4; ++j) {
                    float v = p[mt][rr][j];
                    v += __shfl_xor_sync(0xffffffffu, v, 1);
                    v += __shfl_xor_sync(0xffffffffu, v, 2);
                    p[mt][rr][j] = v;
                }
        float* sO = (float*)smem;     // reuse dead A region, 4 KB
        if (t4 == 0) {
#pragma unroll
            for (int mt = 0; mt < 2; ++mt)
#pragma unroll
                for (int rr = 0; rr < 2; ++rr) {
                    const int rloc = warp_m * 32 + mt * 16 + rr * 8 + g;
#pragma unroll
                    for (int j = 0; j < 4; ++j)
                        sO[rloc * 8 + warp_n * 4 + j] = p[mt][rr][j];
                }
        }
        __syncthreads();
#pragma unroll
        for (int it = 0; it < 2; ++it) {
            const int idx = tid + it * 256;
            const int row = idx >> 2, j = idx & 3;
            out[(size_t)(m0 + row) * 4 + j] = sO[row * 8 + j] + sO[row * 8 + 4 + j] + bo[j];
        }
    }
}

// ---------------- weight fp16-convert + frag-order scatter (K=256) ----------------
__global__ void wsplit_k(const float* __restrict__ w, __half* __restrict__ oh, int K)
{
    const int idx = blockIdx.x * 256 + threadIdx.x;   // = k*256 + n
    const int k = idx >> 8, n = idx & 255;
    const __half hv = __float2half_rn(w[idx]);
    const int ny = n >> 7, nr = n & 127;
    const int nt = nr >> 3, gg = nr & 7;
    const int s = k >> 5, kr = k & 31;
    const int kk = kr >> 4, kr16 = kr & 15;
    const int reg = (kr16 >= 8) ? 1 : 0;
    const int t4 = (kr16 & 7) >> 1;
    const int hp = kr16 & 1;
    const int lane = gg * 4 + t4;
    const int dst = (s * 2 + ny) * 4096 + ((nt * 2 + kk) * 32 + lane) * 4 + reg * 2 + hp;
    oh[dst] = hv;
}

// ---------------- SIMT f32x2 GEMM, 64x64 tiles (node layers, exact fp32) ----------------
template<int MODE, int K, int NOUT, bool RELU>
__global__ __launch_bounds__(256)
void gemm_k64(const float* __restrict__ A, const float* __restrict__ W,
              const float* __restrict__ bias, float* __restrict__ C)
{
    constexpr int TK = 8;
    __shared__ __align__(16) float sA[2][TK][68];
    __shared__ __align__(16) float sB[2][TK][64];

    const int tid = threadIdx.x;
    const int m0 = blockIdx.x * 64, n0 = blockIdx.y * 64;

    // A loader (tid<128), B loader (tid>=128)
    const int a_m = (tid & 127) >> 1, a_k = (tid & 1) << 2;
    const int b_k = (tid & 127) >> 4, b_n = (tid & 15) << 2;

    const int m = m0 + a_m;
    const float* pr;
    if (MODE == MODE_DIR) {
        pr = A + (size_t)m * K;
    } else { // MODE_X
        int b = m / N_, n = m - b * N_;
        pr = A + (size_t)b * (T_ * N_ * D_) + (size_t)n * D_;
    }
    auto ldA = [&](int k0) -> float4 {
        const int k = k0 + a_k;
        if (MODE == MODE_DIR) return *(const float4*)(pr + k);
        return *(const float4*)(pr + (size_t)(k >> 2) * (N_ * D_));
    };
    auto ldB = [&](int k0) -> float4 {
        return *(const float4*)(W + (size_t)(k0 + b_k) * NOUT + n0 + b_n);
    };

    const int tx = tid & 15, ty = tid >> 4;
    u64 acc[4][2];
#pragma unroll
    for (int i = 0; i < 4; i++) { acc[i][0] = 0ull; acc[i][1] = 0ull; }

    constexpr int S = K / TK;
    if (tid < 128) {
        float4 ra = ldA(0);
        sA[0][a_k + 0][a_m] = ra.x; sA[0][a_k + 1][a_m] = ra.y;
        sA[0][a_k + 2][a_m] = ra.z; sA[0][a_k + 3][a_m] = ra.w;
    } else {
        *(float4*)&sB[0][b_k][b_n] = ldB(0);
    }
    __syncthreads();
    for (int s = 0; s < S; ++s) {
        const int cur = s & 1;
        float4 nx;
        if (s + 1 < S) nx = (tid < 128) ? ldA((s + 1) * TK) : ldB((s + 1) * TK);
#pragma unroll
        for (int k = 0; k < TK; ++k) {
            const float4 a = *(const float4*)&sA[cur][k][ty * 4];
            const ulonglong2 b = *(const ulonglong2*)&sB[cur][k][tx * 4];
            u64 ap;
            ap = pk2(a.x, a.x); fma2(acc[0][0], ap, b.x); fma2(acc[0][1], ap, b.y);
            ap = pk2(a.y, a.y); fma2(acc[1][0], ap, b.x); fma2(acc[1][1], ap, b.y);
            ap = pk2(a.z, a.z); fma2(acc[2][0], ap, b.x); fma2(acc[2][1], ap, b.y);
            ap = pk2(a.w, a.w); fma2(acc[3][0], ap, b.x); fma2(acc[3][1], ap, b.y);
        }
        if (s + 1 < S) {
            const int nxt = cur ^ 1;
            if (tid < 128) {
                sA[nxt][a_k + 0][a_m] = nx.x; sA[nxt][a_k + 1][a_m] = nx.y;
                sA[nxt][a_k + 2][a_m] = nx.z; sA[nxt][a_k + 3][a_m] = nx.w;
            } else {
                *(float4*)&sB[nxt][b_k][b_n] = nx;
            }
        }
        __syncthreads();
    }
    const float4 bb = *(const float4*)(bias + n0 + tx * 4);
#pragma unroll
    for (int i = 0; i < 4; ++i) {
        float v0, v1, v2, v3;
        unpk2(v0, v1, acc[i][0]);
        unpk2(v2, v3, acc[i][1]);
        v0 += bb.x; v1 += bb.y; v2 += bb.z; v3 += bb.w;
        if (RELU) {
            v0 = fmaxf(v0, 0.f); v1 = fmaxf(v1, 0.f);
            v2 = fmaxf(v2, 0.f); v3 = fmaxf(v3, 0.f);
        }
        *(float4*)(C + (size_t)(m0 + ty * 4 + i) * NOUT + n0 + tx * 4) =
            make_float4(v0, v1, v2, v3);
    }
}

// ---------------- gemm_pq64: PQ[M,512] = A[M,256] @ {W_top|W_bot} ----------------
// grid (M/64, 8): by>>2 = half (P/Q), (by&3)*64 = n0. Bias only on P half.
__global__ __launch_bounds__(256)
void gemm_pq64(const float* __restrict__ A, const float* __restrict__ W,
               const float* __restrict__ bias, float* __restrict__ C)
{
    constexpr int K = 256, TK = 8;
    __shared__ __align__(16) float sA[2][TK][68];
    __shared__ __align__(16) float sB[2][TK][64];

    const int tid = threadIdx.x;
    const int m0 = blockIdx.x * 64;
    const int half = blockIdx.y >> 2;
    const int n0 = (blockIdx.y & 3) * 64;
    const float* Wb = W + (size_t)half * 256 * 256;

    const int a_m = (tid & 127) >> 1, a_k = (tid & 1) << 2;
    const int b_k = (tid & 127) >> 4, b_n = (tid & 15) << 2;
    const float* pr = A + (size_t)(m0 + a_m) * K;

    auto ldB = [&](int k0) -> float4 {
        return *(const float4*)(Wb + (size_t)(k0 + b_k) * 256 + n0 + b_n);
    };

    const int tx = tid & 15, ty = tid >> 4;
    u64 acc[4][2];
#pragma unroll
    for (int i = 0; i < 4; i++) { acc[i][0] = 0ull; acc[i][1] = 0ull; }

    if (tid < 128) {
        float4 ra = *(const float4*)(pr + a_k);
        sA[0][a_k + 0][a_m] = ra.x; sA[0][a_k + 1][a_m] = ra.y;
        sA[0][a_k + 2][a_m] = ra.z; sA[0][a_k + 3][a_m] = ra.w;
    } else {
        *(float4*)&sB[0][b_k][b_n] = ldB(0);
    }
    __syncthreads();
    for (int s = 0; s < K / TK; ++s) {
        const int cur = s & 1;
        float4 nx;
        if (s + 1 < K / TK)
            nx = (tid < 128) ? *(const float4*)(pr + (s + 1) * TK + a_k) : ldB((s + 1) * TK);
#pragma unroll
        for (int k = 0; k < TK; ++k) {
            const float4 a = *(const float4*)&sA[cur][k][ty * 4];
            const ulonglong2 b = *(const ulonglong2*)&sB[cur][k][tx * 4];
            u64 ap;
            ap = pk2(a.x, a.x); fma2(acc[0][0], ap, b.x); fma2(acc[0][1], ap, b.y);
            ap = pk2(a.y, a.y); fma2(acc[1][0], ap, b.x); fma2(acc[1][1], ap, b.y);
            ap = pk2(a.z, a.z); fma2(acc[2][0], ap, b.x); fma2(acc[2][1], ap, b.y);
            ap = pk2(a.w, a.w); fma2(acc[3][0], ap, b.x); fma2(acc[3][1], ap, b.y);
        }
        if (s + 1 < K / TK) {
            const int nxt = cur ^ 1;
            if (tid < 128) {
                sA[nxt][a_k + 0][a_m] = nx.x; sA[nxt][a_k + 1][a_m] = nx.y;
                sA[nxt][a_k + 2][a_m] = nx.z; sA[nxt][a_k + 3][a_m] = nx.w;
            } else {
                *(float4*)&sB[nxt][b_k][b_n] = nx;
            }
        }
        __syncthreads();
    }
    float4 bb = half ? make_float4(0.f, 0.f, 0.f, 0.f)
                     : *(const float4*)(bias + n0 + tx * 4);
#pragma unroll
    for (int i = 0; i < 4; ++i) {
        float v0, v1, v2, v3;
        unpk2(v0, v1, acc[i][0]);
        unpk2(v2, v3, acc[i][1]);
        v0 += bb.x; v1 += bb.y; v2 += bb.z; v3 += bb.w;
        *(float4*)(C + (size_t)(m0 + ty * 4 + i) * 512 + half * 256 + n0 + tx * 4) =
            make_float4(v0, v1, v2, v3);
    }
}

// ---------------- aggregation (fp16 in, fp32 out) ----------------
__global__ void agg_kernel(const __half* __restrict__ e, float* __restrict__ v)
{
    const int bn = blockIdx.x;
    const int b = bn / N_, n = bn - b * N_;
    const int c = threadIdx.x;
    const __half* base = e + ((size_t)b * E_ + (size_t)n * (N_ - 1)) * H_ + c;
    float s = 0.f;
#pragma unroll 9
    for (int k = 0; k < N_ - 1; ++k) s += __half2float(base[(size_t)k * H_]);
    v[(size_t)bn * H_ + c] = s * (1.0f / N_);
}

// ---------------- launch ----------------
extern "C" void kernel_launch(void* const* d_in, const int* in_sizes, int n_in,
                              void* d_out, int out_size)
{
    (void)in_sizes; (void)n_in; (void)out_size;
    const float* x   = (const float*)d_in[0];
    const float* w1a = (const float*)d_in[3];
    const float* b1a = (const float*)d_in[4];
    const float* w1b = (const float*)d_in[5];
    const float* b1b = (const float*)d_in[6];
    const float* w2a = (const float*)d_in[7];
    const float* b2a = (const float*)d_in[8];
    const float* w2b = (const float*)d_in[9];
    const float* b2b = (const float*)d_in[10];
    const float* w3a = (const float*)d_in[11];
    const float* b3a = (const float*)d_in[12];
    const float* w3b = (const float*)d_in[13];
    const float* b3b = (const float*)d_in[14];
    const float* w4a = (const float*)d_in[15];
    const float* b4a = (const float*)d_in[16];
    const float* w4b = (const float*)d_in[17];
    const float* b4b = (const float*)d_in[18];
    const float* wo  = (const float*)d_in[19];
    const float* bo  = (const float*)d_in[20];
    float* out = (float*)d_out;

    float *xskipf, *nodeA, *nodeB, *pq; __half* wth;
    cudaGetSymbolAddress((void**)&xskipf, g_xskip);
    cudaGetSymbolAddress((void**)&nodeA, g_nodeA);
    cudaGetSymbolAddress((void**)&nodeB, g_nodeB);
    cudaGetSymbolAddress((void**)&pq,    g_pq);
    cudaGetSymbolAddress((void**)&wth,   g_wth);
    __half* xskip16 = (__half*)xskipf;

    __half* f2b = wth;               // w2b, K=256
    __half* f4c = wth + 256 * 256;   // w4a[512:768], K=256 (x_skip block)
    __half* f4b = wth + 512 * 256;   // w4b, K=256

    cudaFuncSetAttribute(fused2, cudaFuncAttributeMaxDynamicSharedMemorySize, F2_BYTES);
    cudaFuncSetAttribute(fused4, cudaFuncAttributeMaxDynamicSharedMemorySize, F4_BYTES);

    // convert+scatter weights into fp16 frag-ordered layout
    wsplit_k<<<256, 256>>>(w2b, f2b, 256);
    wsplit_k<<<256, 256>>>(w4a + 512 * 256, f4c, 256);
    wsplit_k<<<256, 256>>>(w4b, f4b, 256);

    const dim3 blk(256);
    const dim3 gN64(50, 4);
    const dim3 gPQ(50, 8);

    // MLP1 on nodes (SIMT fp32, exact): x -> nodeA(relu) -> nodeB (=h)
    gemm_k64<MODE_X,  NIN_, H_, true ><<<gN64, blk>>>(x,     w1a, b1a, nodeA);
    gemm_k64<MODE_DIR, H_,  H_, false><<<gN64, blk>>>(nodeA, w1b, b1b, nodeB);

    // Node projections for MLP2: PQ = [h@w2a_top + b2a | h@w2a_bot]
    gemm_pq64<<<gPQ, blk>>>(nodeB, w2a, b2a, pq);

    // Fused MLP2 on edges: relu(P[recv]+Q[send]) @ w2b + b2b -> x_skip (fp16)
    fused2<<<2475, blk, F2_BYTES>>>(pq, f2b, b2b, xskip16);

    // Aggregate edges->nodes (fp16 -> fp32)
    agg_kernel<<<B_ * N_, 256>>>(xskip16, nodeA);

    // MLP3 on nodes (SIMT fp32): nodeA -> nodeB(relu) -> nodeA (=v)
    gemm_k64<MODE_DIR, H_, H_, true ><<<gN64, blk>>>(nodeA, w3a, b3a, nodeB);
    gemm_k64<MODE_DIR, H_, H_, false><<<gN64, blk>>>(nodeB, w3b, b3b, nodeA);

    // Node projections for MLP4: PQ = [v@w4a_top + b4a | v@w4a_mid]
    gemm_pq64<<<gPQ, blk>>>(nodeA, w4a, b4a, pq);

    // Fused MLP4 + output head
    fused4<<<2475, blk, F4_BYTES>>>(xskip16, pq, f4c, f4b, b4b, wo, bo, out);
}